// round 5
// baseline (speedup 1.0000x reference)
#include <cuda_runtime.h>
#include <math.h>

#define N_NODES 50000
#define N_EDGES 800000
#define D 128
#define KAGG 512            // 4*D aggregate feature width
#define EPS_STD 1e-5f
#define AVG_DEG_LOG 2.8332133440562162f   // log(17)

#define NBINS 2048          // degree buckets (deg ~ Binomial(800K,1/50K), mean 16)
#define BM 64
#define BN 128
#define BK 16
#define ASTR 68
#define WSTR 132
#define MAX_TILES 3072      // >= ceil(50000/64) + NBINS

// ---------------- scratch (__device__ globals; no allocation allowed) -------
__device__ int   g_cnt[N_NODES];
__device__ int   g_off[N_NODES + 1];
__device__ int   g_woff[N_NODES];
__device__ int   g_perm[N_EDGES];
__device__ float g_agg[(size_t)N_NODES * KAGG];   // [n][512]: mean|min|max|std
// degree-bucket structures
__device__ int   g_bin_cnt[NBINS];
__device__ int   g_bin_off[NBINS + 1];
__device__ int   g_bin_w[NBINS];
__device__ int   g_perm2[N_NODES];                // nodes sorted by degree
__device__ int   g_ntiles;
__device__ int   g_tile_start[MAX_TILES];
__device__ int   g_tile_rows[MAX_TILES];
__device__ int   g_tile_deg[MAX_TILES];

// ---------------- K0: zero counters -----------------------------------------
__global__ void k_zero() {
    int i = blockIdx.x * blockDim.x + threadIdx.x;
    if (i < N_NODES) g_cnt[i] = 0;
    if (i < NBINS)   g_bin_cnt[i] = 0;
    if (i == 0)      g_ntiles = 0;
}

// ---------------- K1: count degrees -----------------------------------------
__global__ void k_count(const int* __restrict__ index) {
    int e = blockIdx.x * blockDim.x + threadIdx.x;
    if (e < N_EDGES) atomicAdd(&g_cnt[index[e]], 1);
}

// ---------------- K2: CSR scan over g_cnt + fused degree-bin histogram ------
__global__ void k_scan() {
    const int n = N_NODES;
    __shared__ int sh_warp[32];
    __shared__ int sh_carry;
    int tid = threadIdx.x, lane = tid & 31, wid = tid >> 5;
    if (tid == 0) sh_carry = 0;
    __syncthreads();
    for (int base = 0; base < n; base += 1024) {
        int i = base + tid;
        int v = (i < n) ? g_cnt[i] : 0;
        if (i < n) {
            int b = v < NBINS ? v : NBINS - 1;
            atomicAdd(&g_bin_cnt[b], 1);          // fused histogram
        }
        int incl = v;
        #pragma unroll
        for (int d = 1; d < 32; d <<= 1) {
            int t = __shfl_up_sync(0xFFFFFFFFu, incl, d);
            if (lane >= d) incl += t;
        }
        if (lane == 31) sh_warp[wid] = incl;
        __syncthreads();
        if (wid == 0) {
            int w = sh_warp[lane];
            int wi = w;
            #pragma unroll
            for (int d = 1; d < 32; d <<= 1) {
                int t = __shfl_up_sync(0xFFFFFFFFu, wi, d);
                if (lane >= d) wi += t;
            }
            sh_warp[lane] = wi - w;
        }
        __syncthreads();
        int excl = incl - v + sh_warp[wid] + sh_carry;
        if (i < n) { g_off[i] = excl; g_woff[i] = excl; }
        __syncthreads();
        if (tid == 1023) sh_carry = excl + v;
        __syncthreads();
    }
    if (tid == 0) g_off[n] = sh_carry;
}

// ---------------- K3: fill CSR permutation ----------------------------------
__global__ void k_fill(const int* __restrict__ index) {
    int e = blockIdx.x * blockDim.x + threadIdx.x;
    if (e < N_EDGES) {
        int node = index[e];
        int pos = atomicAdd(&g_woff[node], 1);
        g_perm[pos] = e;
    }
}

// ---------------- K4: bin scan + fused tile-table build ---------------------
__global__ void k_binscan() {
    __shared__ int sh_warp[32];
    __shared__ int sh_carry;
    int tid = threadIdx.x, lane = tid & 31, wid = tid >> 5;
    if (tid == 0) sh_carry = 0;
    __syncthreads();
    for (int base = 0; base < NBINS; base += 1024) {
        int i = base + tid;
        int v = (i < NBINS) ? g_bin_cnt[i] : 0;
        int incl = v;
        #pragma unroll
        for (int d = 1; d < 32; d <<= 1) {
            int t = __shfl_up_sync(0xFFFFFFFFu, incl, d);
            if (lane >= d) incl += t;
        }
        if (lane == 31) sh_warp[wid] = incl;
        __syncthreads();
        if (wid == 0) {
            int w = sh_warp[lane];
            int wi = w;
            #pragma unroll
            for (int d = 1; d < 32; d <<= 1) {
                int t = __shfl_up_sync(0xFFFFFFFFu, wi, d);
                if (lane >= d) wi += t;
            }
            sh_warp[lane] = wi - w;
        }
        __syncthreads();
        int excl = incl - v + sh_warp[wid] + sh_carry;
        if (i < NBINS) { g_bin_off[i] = excl; g_bin_w[i] = 0; }
        __syncthreads();
        if (tid == 1023) sh_carry = excl + v;
        __syncthreads();
    }
    if (tid == 0) g_bin_off[NBINS] = sh_carry;
    __syncthreads();
    // ---- fused tile-table build (offsets are complete; single block) ----
    for (int b = tid; b < NBINS; b += 1024) {
        int base = g_bin_off[b];
        int cnt = g_bin_off[b + 1] - base;
        for (int j = 0; j < cnt; j += BM) {
            int idx = atomicAdd(&g_ntiles, 1);
            g_tile_start[idx] = base + j;
            g_tile_rows[idx]  = (cnt - j < BM) ? (cnt - j) : BM;
            g_tile_deg[idx]   = b;
        }
    }
}

// ---------------- K5: scatter nodes into degree buckets ---------------------
__global__ void k_fill2() {
    int n = blockIdx.x * blockDim.x + threadIdx.x;
    if (n < N_NODES) {
        int deg = g_cnt[n];
        int b = deg < NBINS ? deg : NBINS - 1;
        int pos = atomicAdd(&g_bin_w[b], 1);
        g_perm2[g_bin_off[b] + pos] = n;
    }
}

// ---------------- K6: gather aggregation, one warp per node -----------------
__global__ void k_agg(const float* __restrict__ x) {
    int n = blockIdx.x * 8 + (threadIdx.x >> 5);
    if (n >= N_NODES) return;
    int lane = threadIdx.x & 31;
    int beg = g_off[n], end = g_off[n + 1];

    float4 s  = make_float4(0.f, 0.f, 0.f, 0.f);
    float4 s2 = make_float4(0.f, 0.f, 0.f, 0.f);
    const float BIG = 3.402823466e38f;
    float4 mn = make_float4( BIG,  BIG,  BIG,  BIG);
    float4 mx = make_float4(-BIG, -BIG, -BIG, -BIG);

    for (int j = beg; j < end; j++) {
        const float4* row = (const float4*)(x + (size_t)g_perm[j] * D);
        float4 v = row[lane];
        s.x += v.x; s.y += v.y; s.z += v.z; s.w += v.w;
        s2.x += v.x * v.x; s2.y += v.y * v.y; s2.z += v.z * v.z; s2.w += v.w * v.w;
        mn.x = fminf(mn.x, v.x); mn.y = fminf(mn.y, v.y); mn.z = fminf(mn.z, v.z); mn.w = fminf(mn.w, v.w);
        mx.x = fmaxf(mx.x, v.x); mx.y = fmaxf(mx.y, v.y); mx.z = fmaxf(mx.z, v.z); mx.w = fmaxf(mx.w, v.w);
    }
    int deg = end - beg;
    float c = fmaxf((float)deg, 1.f);
    float inv = 1.f / c;
    float4 mean = make_float4(s.x * inv, s.y * inv, s.z * inv, s.w * inv);
    float4 sd;
    sd.x = sqrtf(fmaxf(s2.x * inv - mean.x * mean.x, 0.f) + EPS_STD);
    sd.y = sqrtf(fmaxf(s2.y * inv - mean.y * mean.y, 0.f) + EPS_STD);
    sd.z = sqrtf(fmaxf(s2.z * inv - mean.z * mean.z, 0.f) + EPS_STD);
    sd.w = sqrtf(fmaxf(s2.w * inv - mean.w * mean.w, 0.f) + EPS_STD);
    if (deg == 0) {
        mn = make_float4(0.f, 0.f, 0.f, 0.f);
        mx = make_float4(0.f, 0.f, 0.f, 0.f);
    }
    float* o = g_agg + (size_t)n * KAGG;
    ((float4*)(o      ))[lane] = mean;
    ((float4*)(o + 128))[lane] = mn;
    ((float4*)(o + 256))[lane] = mx;
    ((float4*)(o + 384))[lane] = sd;
}

// ---------------- K7: degree-bucketed GEMM, W folded, double-buffered -------
// For a tile of rows all with degree d:
//   out[n,j] = b[j] + sum_{k<512} agg[n,k] * (W[j,k] + a_d*W[j,512+k] + t_d*W[j,1024+k])
__global__ __launch_bounds__(256) void k_gemm3(const float* __restrict__ Wm,
                                               const float* __restrict__ bias,
                                               float* __restrict__ out) {
    int t = blockIdx.x;
    if (t >= g_ntiles) return;
    const int start = g_tile_start[t];
    const int rows  = g_tile_rows[t];
    const int deg   = g_tile_deg[t];
    const float c    = fmaxf((float)deg, 1.f);
    const float logd = logf(c + 1.f);
    const float a_s  = logd / AVG_DEG_LOG;
    const float t_s  = AVG_DEG_LOG / logd;

    __shared__ float As[2][BK][ASTR];
    __shared__ float Ws[2][BK][WSTR];
    __shared__ int   rid[BM];

    const int tid = threadIdx.x;
    if (tid < BM) rid[tid] = (tid < rows) ? g_perm2[start + tid] : -1;
    __syncthreads();

    const int ty = tid >> 4;           // 0..15
    const int tx = tid & 15;           // 0..15
    const int i0 = ty * 4;
    const int j0 = tx * 8;

    const int ar  = tid >> 2;          // 0..63
    const int akq = (tid & 3) * 4;     // 0,4,8,12
    const int an  = rid[ar];
    const float* Arow = g_agg + (size_t)(an >= 0 ? an : 0) * KAGG;

    // per-thread W-fold mapping (2 float4 per thread per tile)
    const int j_w [2] = { (tid * 2    ) >> 2, (tid * 2 + 1) >> 2 };
    const int kq_w[2] = { ((tid * 2    ) & 3) * 4, ((tid * 2 + 1) & 3) * 4 };

    float4 a4;
    float4 wc[2];

    // ---- prologue: load+fold k-tile 0 into buffer 0 ----
    {
        a4 = make_float4(0.f, 0.f, 0.f, 0.f);
        if (an >= 0) a4 = *(const float4*)(Arow + akq);
        #pragma unroll
        for (int u = 0; u < 2; u++) {
            const float* wb = Wm + (size_t)j_w[u] * 1536 + kq_w[u];
            float4 w0 = *(const float4*)(wb);
            float4 w1 = *(const float4*)(wb + 512);
            float4 w2 = *(const float4*)(wb + 1024);
            wc[u].x = w0.x + a_s * w1.x + t_s * w2.x;
            wc[u].y = w0.y + a_s * w1.y + t_s * w2.y;
            wc[u].z = w0.z + a_s * w1.z + t_s * w2.z;
            wc[u].w = w0.w + a_s * w1.w + t_s * w2.w;
        }
        As[0][akq + 0][ar] = a4.x;
        As[0][akq + 1][ar] = a4.y;
        As[0][akq + 2][ar] = a4.z;
        As[0][akq + 3][ar] = a4.w;
        #pragma unroll
        for (int u = 0; u < 2; u++) {
            Ws[0][kq_w[u] + 0][j_w[u]] = wc[u].x;
            Ws[0][kq_w[u] + 1][j_w[u]] = wc[u].y;
            Ws[0][kq_w[u] + 2][j_w[u]] = wc[u].z;
            Ws[0][kq_w[u] + 3][j_w[u]] = wc[u].w;
        }
    }
    __syncthreads();

    float acc[4][8];
    #pragma unroll
    for (int i = 0; i < 4; i++)
        #pragma unroll
        for (int j = 0; j < 8; j++) acc[i][j] = 0.f;

    int buf = 0;
    for (int kt = 0; kt < KAGG; kt += BK) {
        const bool has_next = (kt + BK < KAGG);

        // ---- issue next tile's global loads + fold (overlaps with compute) --
        if (has_next) {
            const int ktn = kt + BK;
            a4 = make_float4(0.f, 0.f, 0.f, 0.f);
            if (an >= 0) a4 = *(const float4*)(Arow + ktn + akq);
            #pragma unroll
            for (int u = 0; u < 2; u++) {
                const float* wb = Wm + (size_t)j_w[u] * 1536 + ktn + kq_w[u];
                float4 w0 = *(const float4*)(wb);
                float4 w1 = *(const float4*)(wb + 512);
                float4 w2 = *(const float4*)(wb + 1024);
                wc[u].x = w0.x + a_s * w1.x + t_s * w2.x;
                wc[u].y = w0.y + a_s * w1.y + t_s * w2.y;
                wc[u].z = w0.z + a_s * w1.z + t_s * w2.z;
                wc[u].w = w0.w + a_s * w1.w + t_s * w2.w;
            }
        }

        // ---- compute on current buffer ----
        #pragma unroll
        for (int k = 0; k < BK; k++) {
            float4 av = *(const float4*)&As[buf][k][i0];
            float4 w0 = *(const float4*)&Ws[buf][k][j0];
            float4 w1 = *(const float4*)&Ws[buf][k][j0 + 4];
            float A[4] = {av.x, av.y, av.z, av.w};
            float B[8] = {w0.x, w0.y, w0.z, w0.w, w1.x, w1.y, w1.z, w1.w};
            #pragma unroll
            for (int i = 0; i < 4; i++)
                #pragma unroll
                for (int j = 0; j < 8; j++)
                    acc[i][j] += A[i] * B[j];
        }

        // ---- store next tile into the other buffer ----
        if (has_next) {
            const int nb = buf ^ 1;
            As[nb][akq + 0][ar] = a4.x;
            As[nb][akq + 1][ar] = a4.y;
            As[nb][akq + 2][ar] = a4.z;
            As[nb][akq + 3][ar] = a4.w;
            #pragma unroll
            for (int u = 0; u < 2; u++) {
                Ws[nb][kq_w[u] + 0][j_w[u]] = wc[u].x;
                Ws[nb][kq_w[u] + 1][j_w[u]] = wc[u].y;
                Ws[nb][kq_w[u] + 2][j_w[u]] = wc[u].z;
                Ws[nb][kq_w[u] + 3][j_w[u]] = wc[u].w;
            }
            __syncthreads();
            buf = nb;
        }
    }

    float4 bj0 = *(const float4*)(bias + j0);
    float4 bj1 = *(const float4*)(bias + j0 + 4);
    #pragma unroll
    for (int i = 0; i < 4; i++) {
        int n = rid[i0 + i];
        if (n >= 0) {
            float4 o0, o1;
            o0.x = acc[i][0] + bj0.x; o0.y = acc[i][1] + bj0.y;
            o0.z = acc[i][2] + bj0.z; o0.w = acc[i][3] + bj0.w;
            o1.x = acc[i][4] + bj1.x; o1.y = acc[i][5] + bj1.y;
            o1.z = acc[i][6] + bj1.z; o1.w = acc[i][7] + bj1.w;
            float* o = out + (size_t)n * D + j0;
            *(float4*)(o)     = o0;
            *(float4*)(o + 4) = o1;
        }
    }
}

// ---------------- launch ----------------------------------------------------
extern "C" void kernel_launch(void* const* d_in, const int* in_sizes, int n_in,
                              void* d_out, int out_size) {
    const float* x     = (const float*)d_in[0];
    const int*   index = (const int*)d_in[1];
    const float* W     = (const float*)d_in[2];
    const float* b     = (const float*)d_in[3];
    float* out = (float*)d_out;

    k_zero<<<(N_NODES + 255) / 256, 256>>>();
    k_count<<<(N_EDGES + 255) / 256, 256>>>(index);
    k_scan<<<1, 1024>>>();
    k_fill<<<(N_EDGES + 255) / 256, 256>>>(index);
    k_binscan<<<1, 1024>>>();
    k_fill2<<<(N_NODES + 255) / 256, 256>>>();
    k_agg<<<(N_NODES + 7) / 8, 256>>>(x);
    k_gemm3<<<MAX_TILES, 256>>>(W, b, out);
}

// round 13
// speedup vs baseline: 1.5075x; 1.5075x over previous
#include <cuda_runtime.h>
#include <cuda_fp16.h>
#include <math.h>
#include <stdint.h>

#define N_NODES 50000
#define N_EDGES 800000
#define D 128
#define KAGG 512            // 4*D aggregate feature width
#define EPS_STD 1e-5f
#define AVG_DEG_LOG 2.8332133440562162f   // log(17)

#define NBINS 2048
#define BM2 128             // GEMM tile rows (nodes)
#define BKT 32              // K per smem tile
#define BKP 40              // padded half-stride (20 words: conflict-free frags)
#define MAX_TILES 2560      // >= ceil(50000/128) + NBINS

// ---------------- scratch (__device__ globals; no allocation allowed) -------
__device__ int   g_cnt[N_NODES];
__device__ int   g_off[N_NODES + 1];
__device__ int   g_woff[N_NODES];
__device__ int   g_perm[N_EDGES];
__device__ float g_agg[(size_t)N_NODES * KAGG];   // [n][512]: mean|min|max|std
__device__ int   g_bin_cnt[NBINS];
__device__ int   g_bin_off[NBINS + 1];
__device__ int   g_bin_w[NBINS];
__device__ int   g_perm2[N_NODES];
__device__ int   g_ntiles;
__device__ int   g_tile_start[MAX_TILES];
__device__ int   g_tile_rows[MAX_TILES];
__device__ int   g_tile_deg[MAX_TILES];

// ---------------- helpers ----------------------------------------------------
__device__ __forceinline__ uint32_t pkh16(__half x, __half y) {
    return (uint32_t)(*(uint16_t*)&x) | ((uint32_t)(*(uint16_t*)&y) << 16);
}

// mma.sync m16n8k16 fp16 in / fp32 accumulate (sm_80+; compiles under compute_103)
__device__ __forceinline__ void mma16816(float* c, const uint32_t* a, const uint32_t* b) {
    asm volatile(
        "mma.sync.aligned.m16n8k16.row.col.f32.f16.f16.f32 "
        "{%0,%1,%2,%3}, {%4,%5,%6,%7}, {%8,%9}, {%0,%1,%2,%3};"
        : "+f"(c[0]), "+f"(c[1]), "+f"(c[2]), "+f"(c[3])
        : "r"(a[0]), "r"(a[1]), "r"(a[2]), "r"(a[3]), "r"(b[0]), "r"(b[1]));
}

// ---------------- K0..K5: CSR + degree buckets (unchanged, passing) ---------
__global__ void k_zero() {
    int i = blockIdx.x * blockDim.x + threadIdx.x;
    if (i < N_NODES) g_cnt[i] = 0;
    if (i < NBINS)   g_bin_cnt[i] = 0;
    if (i == 0)      g_ntiles = 0;
}

__global__ void k_count(const int* __restrict__ index) {
    int e = blockIdx.x * blockDim.x + threadIdx.x;
    if (e < N_EDGES) atomicAdd(&g_cnt[index[e]], 1);
}

__global__ void k_scan() {
    const int n = N_NODES;
    __shared__ int sh_warp[32];
    __shared__ int sh_carry;
    int tid = threadIdx.x, lane = tid & 31, wid = tid >> 5;
    if (tid == 0) sh_carry = 0;
    __syncthreads();
    for (int base = 0; base < n; base += 1024) {
        int i = base + tid;
        int v = (i < n) ? g_cnt[i] : 0;
        if (i < n) {
            int b = v < NBINS ? v : NBINS - 1;
            atomicAdd(&g_bin_cnt[b], 1);
        }
        int incl = v;
        #pragma unroll
        for (int d = 1; d < 32; d <<= 1) {
            int t = __shfl_up_sync(0xFFFFFFFFu, incl, d);
            if (lane >= d) incl += t;
        }
        if (lane == 31) sh_warp[wid] = incl;
        __syncthreads();
        if (wid == 0) {
            int w = sh_warp[lane];
            int wi = w;
            #pragma unroll
            for (int d = 1; d < 32; d <<= 1) {
                int t = __shfl_up_sync(0xFFFFFFFFu, wi, d);
                if (lane >= d) wi += t;
            }
            sh_warp[lane] = wi - w;
        }
        __syncthreads();
        int excl = incl - v + sh_warp[wid] + sh_carry;
        if (i < n) { g_off[i] = excl; g_woff[i] = excl; }
        __syncthreads();
        if (tid == 1023) sh_carry = excl + v;
        __syncthreads();
    }
    if (tid == 0) g_off[n] = sh_carry;
}

__global__ void k_fill(const int* __restrict__ index) {
    int e = blockIdx.x * blockDim.x + threadIdx.x;
    if (e < N_EDGES) {
        int node = index[e];
        int pos = atomicAdd(&g_woff[node], 1);
        g_perm[pos] = e;
    }
}

__global__ void k_binscan() {
    __shared__ int sh_warp[32];
    __shared__ int sh_carry;
    int tid = threadIdx.x, lane = tid & 31, wid = tid >> 5;
    if (tid == 0) sh_carry = 0;
    __syncthreads();
    for (int base = 0; base < NBINS; base += 1024) {
        int i = base + tid;
        int v = (i < NBINS) ? g_bin_cnt[i] : 0;
        int incl = v;
        #pragma unroll
        for (int d = 1; d < 32; d <<= 1) {
            int t = __shfl_up_sync(0xFFFFFFFFu, incl, d);
            if (lane >= d) incl += t;
        }
        if (lane == 31) sh_warp[wid] = incl;
        __syncthreads();
        if (wid == 0) {
            int w = sh_warp[lane];
            int wi = w;
            #pragma unroll
            for (int d = 1; d < 32; d <<= 1) {
                int t = __shfl_up_sync(0xFFFFFFFFu, wi, d);
                if (lane >= d) wi += t;
            }
            sh_warp[lane] = wi - w;
        }
        __syncthreads();
        int excl = incl - v + sh_warp[wid] + sh_carry;
        if (i < NBINS) { g_bin_off[i] = excl; g_bin_w[i] = 0; }
        __syncthreads();
        if (tid == 1023) sh_carry = excl + v;
        __syncthreads();
    }
    if (tid == 0) g_bin_off[NBINS] = sh_carry;
    __syncthreads();
    for (int b = tid; b < NBINS; b += 1024) {
        int base = g_bin_off[b];
        int cnt = g_bin_off[b + 1] - base;
        for (int j = 0; j < cnt; j += BM2) {
            int idx = atomicAdd(&g_ntiles, 1);
            g_tile_start[idx] = base + j;
            g_tile_rows[idx]  = (cnt - j < BM2) ? (cnt - j) : BM2;
            g_tile_deg[idx]   = b;
        }
    }
}

__global__ void k_fill2() {
    int n = blockIdx.x * blockDim.x + threadIdx.x;
    if (n < N_NODES) {
        int deg = g_cnt[n];
        int b = deg < NBINS ? deg : NBINS - 1;
        int pos = atomicAdd(&g_bin_w[b], 1);
        g_perm2[g_bin_off[b] + pos] = n;
    }
}

// ---------------- K6: gather aggregation (unchanged, passing) ---------------
__global__ void k_agg(const float* __restrict__ x) {
    int n = blockIdx.x * 8 + (threadIdx.x >> 5);
    if (n >= N_NODES) return;
    int lane = threadIdx.x & 31;
    int beg = g_off[n], end = g_off[n + 1];

    float4 s  = make_float4(0.f, 0.f, 0.f, 0.f);
    float4 s2 = make_float4(0.f, 0.f, 0.f, 0.f);
    const float BIG = 3.402823466e38f;
    float4 mn = make_float4( BIG,  BIG,  BIG,  BIG);
    float4 mx = make_float4(-BIG, -BIG, -BIG, -BIG);

    for (int j = beg; j < end; j++) {
        const float4* row = (const float4*)(x + (size_t)g_perm[j] * D);
        float4 v = row[lane];
        s.x += v.x; s.y += v.y; s.z += v.z; s.w += v.w;
        s2.x += v.x * v.x; s2.y += v.y * v.y; s2.z += v.z * v.z; s2.w += v.w * v.w;
        mn.x = fminf(mn.x, v.x); mn.y = fminf(mn.y, v.y); mn.z = fminf(mn.z, v.z); mn.w = fminf(mn.w, v.w);
        mx.x = fmaxf(mx.x, v.x); mx.y = fmaxf(mx.y, v.y); mx.z = fmaxf(mx.z, v.z); mx.w = fmaxf(mx.w, v.w);
    }
    int deg = end - beg;
    float c = fmaxf((float)deg, 1.f);
    float inv = 1.f / c;
    float4 mean = make_float4(s.x * inv, s.y * inv, s.z * inv, s.w * inv);
    float4 sd;
    sd.x = sqrtf(fmaxf(s2.x * inv - mean.x * mean.x, 0.f) + EPS_STD);
    sd.y = sqrtf(fmaxf(s2.y * inv - mean.y * mean.y, 0.f) + EPS_STD);
    sd.z = sqrtf(fmaxf(s2.z * inv - mean.z * mean.z, 0.f) + EPS_STD);
    sd.w = sqrtf(fmaxf(s2.w * inv - mean.w * mean.w, 0.f) + EPS_STD);
    if (deg == 0) {
        mn = make_float4(0.f, 0.f, 0.f, 0.f);
        mx = make_float4(0.f, 0.f, 0.f, 0.f);
    }
    float* o = g_agg + (size_t)n * KAGG;
    ((float4*)(o      ))[lane] = mean;
    ((float4*)(o + 128))[lane] = mn;
    ((float4*)(o + 256))[lane] = mx;
    ((float4*)(o + 384))[lane] = sd;
}

// ---------------- K7: mma.sync GEMM, fp16 3-pass split, W folded per tile ---
// out[n,:] = bias + agg[n,:] @ Wfold(deg)^T,  Wfold = W0 + a_d*W1 + t_d*W2
// Split: x = hi + lo (fp16); acc += Ahi*Bhi + Ahi*Blo + Alo*Bhi (drop lo*lo ~2^-22)
__global__ __launch_bounds__(256, 2) void k_gemm_mma(const float* __restrict__ Wm,
                                                     const float* __restrict__ bias,
                                                     float* __restrict__ out) {
    int t = blockIdx.x;
    if (t >= g_ntiles) return;

    __shared__ uint16_t As_hi[BM2][BKP];
    __shared__ uint16_t As_lo[BM2][BKP];
    __shared__ uint16_t Bs_hi[BM2][BKP];
    __shared__ uint16_t Bs_lo[BM2][BKP];
    __shared__ int rid[BM2];

    const int tid  = threadIdx.x;
    const int wid  = tid >> 5;
    const int lane = tid & 31;
    const int wr   = wid >> 1;       // 0..3  (32-row band)
    const int wc   = wid & 1;        // 0..1  (64-col band)
    const int g    = lane >> 2;      // 0..7
    const int tq   = lane & 3;       // 0..3

    const int start = g_tile_start[t];
    const int rows  = g_tile_rows[t];
    const int deg   = g_tile_deg[t];
    const float dc   = fmaxf((float)deg, 1.f);
    const float logd = logf(dc + 1.f);
    const float a_s  = logd / AVG_DEG_LOG;
    const float t_s  = AVG_DEG_LOG / logd;

    if (tid < BM2) rid[tid] = (tid < rows) ? g_perm2[start + tid] : -1;
    __syncthreads();

    float acc[2][8][4];
    #pragma unroll
    for (int mt = 0; mt < 2; mt++)
        #pragma unroll
        for (int nt = 0; nt < 8; nt++)
            #pragma unroll
            for (int i = 0; i < 4; i++) acc[mt][nt][i] = 0.f;

    for (int kt = 0; kt < KAGG; kt += BKT) {
        if (kt) __syncthreads();      // protect previous tile reads

        // ---- load A tile (fp32 -> fp16 hi/lo) ----
        #pragma unroll
        for (int i = 0; i < 4; i++) {
            int idx = i * 256 + tid;          // 0..1023
            int row = idx >> 3;               // 0..127
            int kq  = (idx & 7) * 4;          // 0..28
            int nd  = rid[row];
            float4 v = make_float4(0.f, 0.f, 0.f, 0.f);
            if (nd >= 0) v = *(const float4*)(g_agg + (size_t)nd * KAGG + kt + kq);
            __half h0 = __float2half_rn(v.x), h1 = __float2half_rn(v.y);
            __half h2 = __float2half_rn(v.z), h3 = __float2half_rn(v.w);
            __half l0 = __float2half_rn(v.x - __half2float(h0));
            __half l1 = __float2half_rn(v.y - __half2float(h1));
            __half l2 = __float2half_rn(v.z - __half2float(h2));
            __half l3 = __float2half_rn(v.w - __half2float(h3));
            *(uint2*)&As_hi[row][kq] = make_uint2(pkh16(h0, h1), pkh16(h2, h3));
            *(uint2*)&As_lo[row][kq] = make_uint2(pkh16(l0, l1), pkh16(l2, l3));
        }
        // ---- load B tile: fold 3 W panels, fp32 -> fp16 hi/lo ----
        #pragma unroll
        for (int i = 0; i < 4; i++) {
            int idx = i * 256 + tid;
            int j  = idx >> 3;                // 0..127 (output col)
            int kq = (idx & 7) * 4;
            const float* wb = Wm + (size_t)j * 1536 + kt + kq;
            float4 w0 = *(const float4*)(wb);
            float4 w1 = *(const float4*)(wb + 512);
            float4 w2 = *(const float4*)(wb + 1024);
            float f0 = w0.x + a_s * w1.x + t_s * w2.x;
            float f1 = w0.y + a_s * w1.y + t_s * w2.y;
            float f2 = w0.z + a_s * w1.z + t_s * w2.z;
            float f3 = w0.w + a_s * w1.w + t_s * w2.w;
            __half h0 = __float2half_rn(f0), h1 = __float2half_rn(f1);
            __half h2 = __float2half_rn(f2), h3 = __float2half_rn(f3);
            __half l0 = __float2half_rn(f0 - __half2float(h0));
            __half l1 = __float2half_rn(f1 - __half2float(h1));
            __half l2 = __float2half_rn(f2 - __half2float(h2));
            __half l3 = __float2half_rn(f3 - __half2float(h3));
            *(uint2*)&Bs_hi[j][kq] = make_uint2(pkh16(h0, h1), pkh16(h2, h3));
            *(uint2*)&Bs_lo[j][kq] = make_uint2(pkh16(l0, l1), pkh16(l2, l3));
        }
        __syncthreads();

        // ---- compute: 2 k-steps of 16 ----
        #pragma unroll
        for (int ks = 0; ks < BKT; ks += 16) {
            int k0 = ks + 2 * tq;
            // B fragments for 8 n-tiles (hi + lo)
            uint32_t bh[8][2], bl[8][2];
            #pragma unroll
            for (int nt = 0; nt < 8; nt++) {
                int colB = wc * 64 + nt * 8 + g;
                bh[nt][0] = *(const uint32_t*)&Bs_hi[colB][k0];
                bh[nt][1] = *(const uint32_t*)&Bs_hi[colB][k0 + 8];
                bl[nt][0] = *(const uint32_t*)&Bs_lo[colB][k0];
                bl[nt][1] = *(const uint32_t*)&Bs_lo[colB][k0 + 8];
            }
            #pragma unroll
            for (int mt = 0; mt < 2; mt++) {
                int rowA = wr * 32 + mt * 16 + g;
                uint32_t ah[4], al[4];
                ah[0] = *(const uint32_t*)&As_hi[rowA    ][k0];
                ah[1] = *(const uint32_t*)&As_hi[rowA + 8][k0];
                ah[2] = *(const uint32_t*)&As_hi[rowA    ][k0 + 8];
                ah[3] = *(const uint32_t*)&As_hi[rowA + 8][k0 + 8];
                al[0] = *(const uint32_t*)&As_lo[rowA    ][k0];
                al[1] = *(const uint32_t*)&As_lo[rowA + 8][k0];
                al[2] = *(const uint32_t*)&As_lo[rowA    ][k0 + 8];
                al[3] = *(const uint32_t*)&As_lo[rowA + 8][k0 + 8];
                #pragma unroll
                for (int nt = 0; nt < 8; nt++) {
                    mma16816(acc[mt][nt], ah, bh[nt]);   // hi*hi
                    mma16816(acc[mt][nt], ah, bl[nt]);   // hi*lo
                    mma16816(acc[mt][nt], al, bh[nt]);   // lo*hi
                }
            }
        }
    }

    // ---- epilogue: add bias, scatter to out rows ----
    #pragma unroll
    for (int mt = 0; mt < 2; mt++) {
        int row0 = wr * 32 + mt * 16 + g;
        int n0 = rid[row0];
        int n1 = rid[row0 + 8];
        #pragma unroll
        for (int nt = 0; nt < 8; nt++) {
            int col = wc * 64 + nt * 8 + 2 * tq;
            float b0 = bias[col], b1 = bias[col + 1];
            if (n0 >= 0) {
                float2 v0 = make_float2(acc[mt][nt][0] + b0, acc[mt][nt][1] + b1);
                *(float2*)(out + (size_t)n0 * D + col) = v0;
            }
            if (n1 >= 0) {
                float2 v1 = make_float2(acc[mt][nt][2] + b0, acc[mt][nt][3] + b1);
                *(float2*)(out + (size_t)n1 * D + col) = v1;
            }
        }
    }
}

// ---------------- launch ----------------------------------------------------
extern "C" void kernel_launch(void* const* d_in, const int* in_sizes, int n_in,
                              void* d_out, int out_size) {
    const float* x     = (const float*)d_in[0];
    const int*   index = (const int*)d_in[1];
    const float* W     = (const float*)d_in[2];
    const float* b     = (const float*)d_in[3];
    float* out = (float*)d_out;

    k_zero<<<(N_NODES + 255) / 256, 256>>>();
    k_count<<<(N_EDGES + 255) / 256, 256>>>(index);
    k_scan<<<1, 1024>>>();
    k_fill<<<(N_EDGES + 255) / 256, 256>>>(index);
    k_binscan<<<1, 1024>>>();
    k_fill2<<<(N_NODES + 255) / 256, 256>>>();
    k_agg<<<(N_NODES + 7) / 8, 256>>>(x);
    k_gemm_mma<<<MAX_TILES, 256>>>(W, b, out);
}

// round 14
// speedup vs baseline: 1.6693x; 1.1073x over previous
#include <cuda_runtime.h>
#include <cuda_fp16.h>
#include <math.h>
#include <stdint.h>

#define N_NODES 50000
#define N_EDGES 800000
#define D 128
#define KAGG 512            // 4*D aggregate feature width
#define EPS_STD 1e-5f
#define AVG_DEG_LOG 2.8332133440562162f   // log(17)

#define NBINS 2048
#define BM2 128             // GEMM tile rows (nodes)
#define BKT 32              // K per smem tile
#define BKP 40              // padded half-stride (20 words: conflict-free frags)
#define MAX_TILES 2560      // >= ceil(50000/128) + NBINS
#define MAX_SLOTS 256       // distinct degrees (Poisson(16): ~40 in practice)

// ---------------- scratch (__device__ globals; no allocation allowed) -------
__device__ int      g_cnt[N_NODES];
__device__ int      g_off[N_NODES + 1];
__device__ int      g_woff[N_NODES];
__device__ int      g_perm[N_EDGES];
__device__ uint16_t g_agg_hi[(size_t)N_NODES * KAGG];  // fp16 hi plane
__device__ uint16_t g_agg_lo[(size_t)N_NODES * KAGG];  // fp16 lo plane
__device__ int      g_bin_cnt[NBINS];
__device__ int      g_bin_off[NBINS + 1];
__device__ int      g_bin_w[NBINS];
__device__ int      g_perm2[N_NODES];
__device__ int      g_ntiles;
__device__ int      g_nslots;
__device__ int      g_slot_deg[MAX_SLOTS];
__device__ int      g_tile_start[MAX_TILES];
__device__ int      g_tile_rows[MAX_TILES];
__device__ int      g_tile_deg[MAX_TILES];
__device__ int      g_tile_slot[MAX_TILES];
__device__ uint16_t g_wf_hi[(size_t)MAX_SLOTS * D * KAGG];  // prefolded W hi
__device__ uint16_t g_wf_lo[(size_t)MAX_SLOTS * D * KAGG];  // prefolded W lo

// ---------------- helpers ----------------------------------------------------
__device__ __forceinline__ uint32_t pkh16(__half x, __half y) {
    return (uint32_t)(*(uint16_t*)&x) | ((uint32_t)(*(uint16_t*)&y) << 16);
}

// mma.sync m16n8k16 fp16 in / fp32 accumulate (sm_80+; compiles under compute_103)
__device__ __forceinline__ void mma16816(float* c, const uint32_t* a, const uint32_t* b) {
    asm volatile(
        "mma.sync.aligned.m16n8k16.row.col.f32.f16.f16.f32 "
        "{%0,%1,%2,%3}, {%4,%5,%6,%7}, {%8,%9}, {%0,%1,%2,%3};"
        : "+f"(c[0]), "+f"(c[1]), "+f"(c[2]), "+f"(c[3])
        : "r"(a[0]), "r"(a[1]), "r"(a[2]), "r"(a[3]), "r"(b[0]), "r"(b[1]));
}

__device__ __forceinline__ void split16(float v, __half& h, __half& l) {
    h = __float2half_rn(v);
    l = __float2half_rn(v - __half2float(h));
}

// ---------------- K0: zero counters -----------------------------------------
__global__ void k_zero() {
    int i = blockIdx.x * blockDim.x + threadIdx.x;
    if (i < N_NODES) g_cnt[i] = 0;
    if (i < NBINS)   g_bin_cnt[i] = 0;
    if (i == 0) { g_ntiles = 0; g_nslots = 0; }
}

// ---------------- K1: count degrees -----------------------------------------
__global__ void k_count(const int* __restrict__ index) {
    int e = blockIdx.x * blockDim.x + threadIdx.x;
    if (e < N_EDGES) atomicAdd(&g_cnt[index[e]], 1);
}

// ---------------- K2: CSR scan + degree histogram ---------------------------
__global__ void k_scan() {
    const int n = N_NODES;
    __shared__ int sh_warp[32];
    __shared__ int sh_carry;
    int tid = threadIdx.x, lane = tid & 31, wid = tid >> 5;
    if (tid == 0) sh_carry = 0;
    __syncthreads();
    for (int base = 0; base < n; base += 1024) {
        int i = base + tid;
        int v = (i < n) ? g_cnt[i] : 0;
        if (i < n) {
            int b = v < NBINS ? v : NBINS - 1;
            atomicAdd(&g_bin_cnt[b], 1);
        }
        int incl = v;
        #pragma unroll
        for (int d = 1; d < 32; d <<= 1) {
            int t = __shfl_up_sync(0xFFFFFFFFu, incl, d);
            if (lane >= d) incl += t;
        }
        if (lane == 31) sh_warp[wid] = incl;
        __syncthreads();
        if (wid == 0) {
            int w = sh_warp[lane];
            int wi = w;
            #pragma unroll
            for (int d = 1; d < 32; d <<= 1) {
                int t = __shfl_up_sync(0xFFFFFFFFu, wi, d);
                if (lane >= d) wi += t;
            }
            sh_warp[lane] = wi - w;
        }
        __syncthreads();
        int excl = incl - v + sh_warp[wid] + sh_carry;
        if (i < n) { g_off[i] = excl; g_woff[i] = excl; }
        __syncthreads();
        if (tid == 1023) sh_carry = excl + v;
        __syncthreads();
    }
    if (tid == 0) g_off[n] = sh_carry;
}

// ---------------- K3: fill CSR permutation ----------------------------------
__global__ void k_fill(const int* __restrict__ index) {
    int e = blockIdx.x * blockDim.x + threadIdx.x;
    if (e < N_EDGES) {
        int node = index[e];
        int pos = atomicAdd(&g_woff[node], 1);
        g_perm[pos] = e;
    }
}

// ---------------- K4: bin scan + slot assignment + tile table ---------------
__global__ void k_binscan() {
    __shared__ int sh_warp[32];
    __shared__ int sh_carry;
    int tid = threadIdx.x, lane = tid & 31, wid = tid >> 5;
    if (tid == 0) sh_carry = 0;
    __syncthreads();
    for (int base = 0; base < NBINS; base += 1024) {
        int i = base + tid;
        int v = (i < NBINS) ? g_bin_cnt[i] : 0;
        int incl = v;
        #pragma unroll
        for (int d = 1; d < 32; d <<= 1) {
            int t = __shfl_up_sync(0xFFFFFFFFu, incl, d);
            if (lane >= d) incl += t;
        }
        if (lane == 31) sh_warp[wid] = incl;
        __syncthreads();
        if (wid == 0) {
            int w = sh_warp[lane];
            int wi = w;
            #pragma unroll
            for (int d = 1; d < 32; d <<= 1) {
                int t = __shfl_up_sync(0xFFFFFFFFu, wi, d);
                if (lane >= d) wi += t;
            }
            sh_warp[lane] = wi - w;
        }
        __syncthreads();
        int excl = incl - v + sh_warp[wid] + sh_carry;
        if (i < NBINS) { g_bin_off[i] = excl; g_bin_w[i] = 0; }
        __syncthreads();
        if (tid == 1023) sh_carry = excl + v;
        __syncthreads();
    }
    if (tid == 0) g_bin_off[NBINS] = sh_carry;
    __syncthreads();
    // slot assignment + degree-homogeneous tile table
    for (int b = tid; b < NBINS; b += 1024) {
        int base = g_bin_off[b];
        int cnt = g_bin_off[b + 1] - base;
        if (cnt > 0) {
            int slot = atomicAdd(&g_nslots, 1);
            if (slot < MAX_SLOTS) g_slot_deg[slot] = b;
            else slot = -1;
            for (int j = 0; j < cnt; j += BM2) {
                int idx = atomicAdd(&g_ntiles, 1);
                g_tile_start[idx] = base + j;
                g_tile_rows[idx]  = (cnt - j < BM2) ? (cnt - j) : BM2;
                g_tile_deg[idx]   = b;
                g_tile_slot[idx]  = slot;
            }
        }
    }
}

// ---------------- K5: scatter nodes into degree buckets ---------------------
__global__ void k_fill2() {
    int n = blockIdx.x * blockDim.x + threadIdx.x;
    if (n < N_NODES) {
        int deg = g_cnt[n];
        int b = deg < NBINS ? deg : NBINS - 1;
        int pos = atomicAdd(&g_bin_w[b], 1);
        g_perm2[g_bin_off[b] + pos] = n;
    }
}

// ---------------- K6: pre-fold W per slot into fp16 hi/lo -------------------
__global__ void k_prefold(const float* __restrict__ Wm) {
    int slot = blockIdx.x;
    if (slot >= g_nslots || slot >= MAX_SLOTS) return;
    int deg = g_slot_deg[slot];
    const float dc   = fmaxf((float)deg, 1.f);
    const float logd = logf(dc + 1.f);
    const float a_s  = logd / AVG_DEG_LOG;
    const float t_s  = AVG_DEG_LOG / logd;

    int part = blockIdx.y;                 // 0..7
    int tid = threadIdx.x;
    size_t sbase = (size_t)slot * D * KAGG;
    #pragma unroll
    for (int it = 0; it < 8; it++) {
        int idx = part * 8192 + it * 1024 + tid * 4;   // 4 elems per thread
        int j = idx >> 9;                  // 0..127
        int k = idx & 511;
        const float* wb = Wm + (size_t)j * 1536 + k;
        float4 w0 = *(const float4*)(wb);
        float4 w1 = *(const float4*)(wb + 512);
        float4 w2 = *(const float4*)(wb + 1024);
        float f0 = w0.x + a_s * w1.x + t_s * w2.x;
        float f1 = w0.y + a_s * w1.y + t_s * w2.y;
        float f2 = w0.z + a_s * w1.z + t_s * w2.z;
        float f3 = w0.w + a_s * w1.w + t_s * w2.w;
        __half h0, h1, h2, h3, l0, l1, l2, l3;
        split16(f0, h0, l0); split16(f1, h1, l1);
        split16(f2, h2, l2); split16(f3, h3, l3);
        *(uint2*)&g_wf_hi[sbase + idx] = make_uint2(pkh16(h0, h1), pkh16(h2, h3));
        *(uint2*)&g_wf_lo[sbase + idx] = make_uint2(pkh16(l0, l1), pkh16(l2, l3));
    }
}

// ---------------- K7: gather aggregation, emit fp16 hi/lo -------------------
__global__ void k_agg(const float* __restrict__ x) {
    int n = blockIdx.x * 8 + (threadIdx.x >> 5);
    if (n >= N_NODES) return;
    int lane = threadIdx.x & 31;
    int beg = g_off[n], end = g_off[n + 1];

    float4 s  = make_float4(0.f, 0.f, 0.f, 0.f);
    float4 s2 = make_float4(0.f, 0.f, 0.f, 0.f);
    const float BIG = 3.402823466e38f;
    float4 mn = make_float4( BIG,  BIG,  BIG,  BIG);
    float4 mx = make_float4(-BIG, -BIG, -BIG, -BIG);

    for (int j = beg; j < end; j++) {
        const float4* row = (const float4*)(x + (size_t)g_perm[j] * D);
        float4 v = row[lane];
        s.x += v.x; s.y += v.y; s.z += v.z; s.w += v.w;
        s2.x += v.x * v.x; s2.y += v.y * v.y; s2.z += v.z * v.z; s2.w += v.w * v.w;
        mn.x = fminf(mn.x, v.x); mn.y = fminf(mn.y, v.y); mn.z = fminf(mn.z, v.z); mn.w = fminf(mn.w, v.w);
        mx.x = fmaxf(mx.x, v.x); mx.y = fmaxf(mx.y, v.y); mx.z = fmaxf(mx.z, v.z); mx.w = fmaxf(mx.w, v.w);
    }
    int deg = end - beg;
    float c = fmaxf((float)deg, 1.f);
    float inv = 1.f / c;
    float4 mean = make_float4(s.x * inv, s.y * inv, s.z * inv, s.w * inv);
    float4 sd;
    sd.x = sqrtf(fmaxf(s2.x * inv - mean.x * mean.x, 0.f) + EPS_STD);
    sd.y = sqrtf(fmaxf(s2.y * inv - mean.y * mean.y, 0.f) + EPS_STD);
    sd.z = sqrtf(fmaxf(s2.z * inv - mean.z * mean.z, 0.f) + EPS_STD);
    sd.w = sqrtf(fmaxf(s2.w * inv - mean.w * mean.w, 0.f) + EPS_STD);
    if (deg == 0) {
        mn = make_float4(0.f, 0.f, 0.f, 0.f);
        mx = make_float4(0.f, 0.f, 0.f, 0.f);
    }
    size_t ob = (size_t)n * KAGG + lane * 4;
    float4 vals[4] = {mean, mn, mx, sd};
    #pragma unroll
    for (int sec = 0; sec < 4; sec++) {
        float4 v = vals[sec];
        __half h0, h1, h2, h3, l0, l1, l2, l3;
        split16(v.x, h0, l0); split16(v.y, h1, l1);
        split16(v.z, h2, l2); split16(v.w, h3, l3);
        *(uint2*)&g_agg_hi[ob + sec * 128] = make_uint2(pkh16(h0, h1), pkh16(h2, h3));
        *(uint2*)&g_agg_lo[ob + sec * 128] = make_uint2(pkh16(l0, l1), pkh16(l2, l3));
    }
}

// ---------------- K8: mma.sync GEMM, prefolded fp16 tiles -------------------
// out[n,:] = bias + agg[n,:] @ Wfold(deg)^T  (fp16 hi/lo 3-pass split)
__global__ __launch_bounds__(256, 2) void k_gemm_mma(const float* __restrict__ Wm,
                                                     const float* __restrict__ bias,
                                                     float* __restrict__ out) {
    int t = blockIdx.x;
    if (t >= g_ntiles) return;

    __shared__ uint16_t As_hi[BM2][BKP];
    __shared__ uint16_t As_lo[BM2][BKP];
    __shared__ uint16_t Bs_hi[BM2][BKP];
    __shared__ uint16_t Bs_lo[BM2][BKP];
    __shared__ int rid[BM2];

    const int tid  = threadIdx.x;
    const int wid  = tid >> 5;
    const int lane = tid & 31;
    const int wr   = wid >> 1;       // 0..3  (32-row band)
    const int wc   = wid & 1;        // 0..1  (64-col band)
    const int g    = lane >> 2;      // 0..7
    const int tq   = lane & 3;       // 0..3

    const int start = g_tile_start[t];
    const int rows  = g_tile_rows[t];
    const int slot  = g_tile_slot[t];
    const int deg   = g_tile_deg[t];
    const float dc   = fmaxf((float)deg, 1.f);
    const float logd = logf(dc + 1.f);
    const float a_s  = logd / AVG_DEG_LOG;
    const float t_s  = AVG_DEG_LOG / logd;

    if (tid < BM2) rid[tid] = (tid < rows) ? g_perm2[start + tid] : -1;
    __syncthreads();

    float acc[2][8][4];
    #pragma unroll
    for (int mt = 0; mt < 2; mt++)
        #pragma unroll
        for (int nt = 0; nt < 8; nt++)
            #pragma unroll
            for (int i = 0; i < 4; i++) acc[mt][nt][i] = 0.f;

    const size_t wfb = (size_t)(slot >= 0 ? slot : 0) * D * KAGG;

    for (int kt = 0; kt < KAGG; kt += BKT) {
        if (kt) __syncthreads();

        // ---- A tile: direct fp16 hi/lo copies ----
        #pragma unroll
        for (int i = 0; i < 4; i++) {
            int idx = i * 256 + tid;          // 0..1023
            int row = idx >> 3;               // 0..127
            int kq  = (idx & 7) * 4;          // 0..28
            int nd  = rid[row];
            uint2 vh = make_uint2(0u, 0u), vl = make_uint2(0u, 0u);
            if (nd >= 0) {
                size_t ab = (size_t)nd * KAGG + kt + kq;
                vh = *(const uint2*)&g_agg_hi[ab];
                vl = *(const uint2*)&g_agg_lo[ab];
            }
            *(uint2*)&As_hi[row][kq] = vh;
            *(uint2*)&As_lo[row][kq] = vl;
        }
        // ---- B tile: prefolded fp16 copies (fallback: in-kernel fold) ----
        if (slot >= 0) {
            #pragma unroll
            for (int i = 0; i < 4; i++) {
                int idx = i * 256 + tid;
                int j  = idx >> 3;
                int kq = (idx & 7) * 4;
                size_t bb = wfb + (size_t)j * KAGG + kt + kq;
                *(uint2*)&Bs_hi[j][kq] = *(const uint2*)&g_wf_hi[bb];
                *(uint2*)&Bs_lo[j][kq] = *(const uint2*)&g_wf_lo[bb];
            }
        } else {
            #pragma unroll
            for (int i = 0; i < 4; i++) {
                int idx = i * 256 + tid;
                int j  = idx >> 3;
                int kq = (idx & 7) * 4;
                const float* wb = Wm + (size_t)j * 1536 + kt + kq;
                float4 w0 = *(const float4*)(wb);
                float4 w1 = *(const float4*)(wb + 512);
                float4 w2 = *(const float4*)(wb + 1024);
                float f0 = w0.x + a_s * w1.x + t_s * w2.x;
                float f1 = w0.y + a_s * w1.y + t_s * w2.y;
                float f2 = w0.z + a_s * w1.z + t_s * w2.z;
                float f3 = w0.w + a_s * w1.w + t_s * w2.w;
                __half h0, h1, h2, h3, l0, l1, l2, l3;
                split16(f0, h0, l0); split16(f1, h1, l1);
                split16(f2, h2, l2); split16(f3, h3, l3);
                *(uint2*)&Bs_hi[j][kq] = make_uint2(pkh16(h0, h1), pkh16(h2, h3));
                *(uint2*)&Bs_lo[j][kq] = make_uint2(pkh16(l0, l1), pkh16(l2, l3));
            }
        }
        __syncthreads();

        // ---- compute: 2 k-steps of 16 ----
        #pragma unroll
        for (int ks = 0; ks < BKT; ks += 16) {
            int k0 = ks + 2 * tq;
            uint32_t bh[8][2], bl[8][2];
            #pragma unroll
            for (int nt = 0; nt < 8; nt++) {
                int colB = wc * 64 + nt * 8 + g;
                bh[nt][0] = *(const uint32_t*)&Bs_hi[colB][k0];
                bh[nt][1] = *(const uint32_t*)&Bs_hi[colB][k0 + 8];
                bl[nt][0] = *(const uint32_t*)&Bs_lo[colB][k0];
                bl[nt][1] = *(const uint32_t*)&Bs_lo[colB][k0 + 8];
            }
            #pragma unroll
            for (int mt = 0; mt < 2; mt++) {
                int rowA = wr * 32 + mt * 16 + g;
                uint32_t ah[4], al[4];
                ah[0] = *(const uint32_t*)&As_hi[rowA    ][k0];
                ah[1] = *(const uint32_t*)&As_hi[rowA + 8][k0];
                ah[2] = *(const uint32_t*)&As_hi[rowA    ][k0 + 8];
                ah[3] = *(const uint32_t*)&As_hi[rowA + 8][k0 + 8];
                al[0] = *(const uint32_t*)&As_lo[rowA    ][k0];
                al[1] = *(const uint32_t*)&As_lo[rowA + 8][k0];
                al[2] = *(const uint32_t*)&As_lo[rowA    ][k0 + 8];
                al[3] = *(const uint32_t*)&As_lo[rowA + 8][k0 + 8];
                #pragma unroll
                for (int nt = 0; nt < 8; nt++) {
                    mma16816(acc[mt][nt], ah, bh[nt]);   // hi*hi
                    mma16816(acc[mt][nt], ah, bl[nt]);   // hi*lo
                    mma16816(acc[mt][nt], al, bh[nt]);   // lo*hi
                }
            }
        }
    }

    // ---- epilogue: add bias, scatter to out rows ----
    #pragma unroll
    for (int mt = 0; mt < 2; mt++) {
        int row0 = wr * 32 + mt * 16 + g;
        int n0 = rid[row0];
        int n1 = rid[row0 + 8];
        #pragma unroll
        for (int nt = 0; nt < 8; nt++) {
            int col = wc * 64 + nt * 8 + 2 * tq;
            float b0 = bias[col], b1 = bias[col + 1];
            if (n0 >= 0) {
                float2 v0 = make_float2(acc[mt][nt][0] + b0, acc[mt][nt][1] + b1);
                *(float2*)(out + (size_t)n0 * D + col) = v0;
            }
            if (n1 >= 0) {
                float2 v1 = make_float2(acc[mt][nt][2] + b0, acc[mt][nt][3] + b1);
                *(float2*)(out + (size_t)n1 * D + col) = v1;
            }
        }
    }
}

// ---------------- launch ----------------------------------------------------
extern "C" void kernel_launch(void* const* d_in, const int* in_sizes, int n_in,
                              void* d_out, int out_size) {
    const float* x     = (const float*)d_in[0];
    const int*   index = (const int*)d_in[1];
    const float* W     = (const float*)d_in[2];
    const float* b     = (const float*)d_in[3];
    float* out = (float*)d_out;

    k_zero<<<(N_NODES + 255) / 256, 256>>>();
    k_count<<<(N_EDGES + 255) / 256, 256>>>(index);
    k_scan<<<1, 1024>>>();
    k_fill<<<(N_EDGES + 255) / 256, 256>>>(index);
    k_binscan<<<1, 1024>>>();
    k_prefold<<<dim3(MAX_SLOTS, 8), 256>>>(W);
    k_fill2<<<(N_NODES + 255) / 256, 256>>>();
    k_agg<<<(N_NODES + 7) / 8, 256>>>(x);
    k_gemm_mma<<<MAX_TILES, 256>>>(W, b, out);
}

// round 15
// speedup vs baseline: 1.9369x; 1.1603x over previous
#include <cuda_runtime.h>
#include <cuda_fp16.h>
#include <math.h>
#include <stdint.h>

#define N_NODES 50000
#define N_EDGES 800000
#define D 128
#define KAGG 512            // 4*D aggregate feature width
#define EPS_STD 1e-5f
#define AVG_DEG_LOG 2.8332133440562162f   // log(17)

#define NBINS 2048
#define BM2 128             // GEMM tile rows (nodes)
#define BKT 32              // K per smem tile
#define BKP 40              // padded half-stride (20 words: conflict-free frags)
#define MAX_TILES 2560
#define MAX_SLOTS 256

#define ARR_BYTES (BM2 * BKP * 2)          // 10240 per plane
#define STAGE_BYTES (4 * ARR_BYTES)        // 40960
#define SMEM_GEMM (2 * STAGE_BYTES + 512)  // 82432

// ---------------- scratch (__device__ globals; no allocation allowed) -------
__device__ int      g_cnt[N_NODES];
__device__ int      g_off[N_NODES + 1];
__device__ int      g_woff[N_NODES];
__device__ int      g_perm[N_EDGES];
__device__ uint16_t g_agg_hi[(size_t)N_NODES * KAGG];
__device__ uint16_t g_agg_lo[(size_t)N_NODES * KAGG];
__device__ int      g_bin_cnt[NBINS];
__device__ int      g_bin_off[NBINS + 1];
__device__ int      g_bin_w[NBINS];
__device__ int      g_perm2[N_NODES];
__device__ int      g_ntiles;
__device__ int      g_nslots;
__device__ int      g_slot_deg[MAX_SLOTS];
__device__ int      g_tile_start[MAX_TILES];
__device__ int      g_tile_rows[MAX_TILES];
__device__ int      g_tile_deg[MAX_TILES];
__device__ int      g_tile_slot[MAX_TILES];
__device__ uint16_t g_wf_hi[(size_t)MAX_SLOTS * D * KAGG];
__device__ uint16_t g_wf_lo[(size_t)MAX_SLOTS * D * KAGG];

// ---------------- helpers ----------------------------------------------------
__device__ __forceinline__ uint32_t pkh16(__half x, __half y) {
    return (uint32_t)(*(uint16_t*)&x) | ((uint32_t)(*(uint16_t*)&y) << 16);
}
__device__ __forceinline__ void mma16816(float* c, const uint32_t* a, const uint32_t* b) {
    asm volatile(
        "mma.sync.aligned.m16n8k16.row.col.f32.f16.f16.f32 "
        "{%0,%1,%2,%3}, {%4,%5,%6,%7}, {%8,%9}, {%0,%1,%2,%3};"
        : "+f"(c[0]), "+f"(c[1]), "+f"(c[2]), "+f"(c[3])
        : "r"(a[0]), "r"(a[1]), "r"(a[2]), "r"(a[3]), "r"(b[0]), "r"(b[1]));
}
__device__ __forceinline__ void split16(float v, __half& h, __half& l) {
    h = __float2half_rn(v);
    l = __float2half_rn(v - __half2float(h));
}
#define CP16(dst, src, sz) \
    asm volatile("cp.async.cg.shared.global [%0], [%1], 16, %2;" \
                 :: "r"(dst), "l"(src), "r"(sz) : "memory")
#define CP_COMMIT() asm volatile("cp.async.commit_group;" ::: "memory")
#define CP_WAIT(n)  asm volatile("cp.async.wait_group %0;" :: "n"(n) : "memory")

// ---------------- K0: zero counters -----------------------------------------
__global__ void k_zero() {
    int i = blockIdx.x * blockDim.x + threadIdx.x;
    if (i < N_NODES) g_cnt[i] = 0;
    if (i < NBINS)   g_bin_cnt[i] = 0;
    if (i == 0) { g_ntiles = 0; g_nslots = 0; }
}

// ---------------- K1: count degrees -----------------------------------------
__global__ void k_count(const int* __restrict__ index) {
    int e = blockIdx.x * blockDim.x + threadIdx.x;
    if (e < N_EDGES) atomicAdd(&g_cnt[index[e]], 1);
}

// ---------------- K2: CSR scan + degree histogram ---------------------------
__global__ void k_scan() {
    const int n = N_NODES;
    __shared__ int sh_warp[32];
    __shared__ int sh_carry;
    int tid = threadIdx.x, lane = tid & 31, wid = tid >> 5;
    if (tid == 0) sh_carry = 0;
    __syncthreads();
    for (int base = 0; base < n; base += 1024) {
        int i = base + tid;
        int v = (i < n) ? g_cnt[i] : 0;
        if (i < n) {
            int b = v < NBINS ? v : NBINS - 1;
            atomicAdd(&g_bin_cnt[b], 1);
        }
        int incl = v;
        #pragma unroll
        for (int d = 1; d < 32; d <<= 1) {
            int t = __shfl_up_sync(0xFFFFFFFFu, incl, d);
            if (lane >= d) incl += t;
        }
        if (lane == 31) sh_warp[wid] = incl;
        __syncthreads();
        if (wid == 0) {
            int w = sh_warp[lane];
            int wi = w;
            #pragma unroll
            for (int d = 1; d < 32; d <<= 1) {
                int t = __shfl_up_sync(0xFFFFFFFFu, wi, d);
                if (lane >= d) wi += t;
            }
            sh_warp[lane] = wi - w;
        }
        __syncthreads();
        int excl = incl - v + sh_warp[wid] + sh_carry;
        if (i < n) { g_off[i] = excl; g_woff[i] = excl; }
        __syncthreads();
        if (tid == 1023) sh_carry = excl + v;
        __syncthreads();
    }
    if (tid == 0) g_off[n] = sh_carry;
}

// ---------------- K3: fill CSR permutation ----------------------------------
__global__ void k_fill(const int* __restrict__ index) {
    int e = blockIdx.x * blockDim.x + threadIdx.x;
    if (e < N_EDGES) {
        int node = index[e];
        int pos = atomicAdd(&g_woff[node], 1);
        g_perm[pos] = e;
    }
}

// ---------------- K4: bin scan + slot assignment + tile table ---------------
__global__ void k_binscan() {
    __shared__ int sh_warp[32];
    __shared__ int sh_carry;
    int tid = threadIdx.x, lane = tid & 31, wid = tid >> 5;
    if (tid == 0) sh_carry = 0;
    __syncthreads();
    for (int base = 0; base < NBINS; base += 1024) {
        int i = base + tid;
        int v = (i < NBINS) ? g_bin_cnt[i] : 0;
        int incl = v;
        #pragma unroll
        for (int d = 1; d < 32; d <<= 1) {
            int t = __shfl_up_sync(0xFFFFFFFFu, incl, d);
            if (lane >= d) incl += t;
        }
        if (lane == 31) sh_warp[wid] = incl;
        __syncthreads();
        if (wid == 0) {
            int w = sh_warp[lane];
            int wi = w;
            #pragma unroll
            for (int d = 1; d < 32; d <<= 1) {
                int t = __shfl_up_sync(0xFFFFFFFFu, wi, d);
                if (lane >= d) wi += t;
            }
            sh_warp[lane] = wi - w;
        }
        __syncthreads();
        int excl = incl - v + sh_warp[wid] + sh_carry;
        if (i < NBINS) { g_bin_off[i] = excl; g_bin_w[i] = 0; }
        __syncthreads();
        if (tid == 1023) sh_carry = excl + v;
        __syncthreads();
    }
    if (tid == 0) g_bin_off[NBINS] = sh_carry;
    __syncthreads();
    for (int b = tid; b < NBINS; b += 1024) {
        int base = g_bin_off[b];
        int cnt = g_bin_off[b + 1] - base;
        if (cnt > 0) {
            int slot = atomicAdd(&g_nslots, 1);
            if (slot < MAX_SLOTS) g_slot_deg[slot] = b;
            else slot = -1;
            for (int j = 0; j < cnt; j += BM2) {
                int idx = atomicAdd(&g_ntiles, 1);
                g_tile_start[idx] = base + j;
                g_tile_rows[idx]  = (cnt - j < BM2) ? (cnt - j) : BM2;
                g_tile_deg[idx]   = b;
                g_tile_slot[idx]  = slot;
            }
        }
    }
}

// ---------------- K5: scatter nodes into degree buckets ---------------------
__global__ void k_fill2() {
    int n = blockIdx.x * blockDim.x + threadIdx.x;
    if (n < N_NODES) {
        int deg = g_cnt[n];
        int b = deg < NBINS ? deg : NBINS - 1;
        int pos = atomicAdd(&g_bin_w[b], 1);
        g_perm2[g_bin_off[b] + pos] = n;
    }
}

// ---------------- K6: pre-fold W per slot into fp16 hi/lo -------------------
__global__ void k_prefold(const float* __restrict__ Wm) {
    int slot = blockIdx.x;
    if (slot >= g_nslots || slot >= MAX_SLOTS) return;
    int deg = g_slot_deg[slot];
    const float dc   = fmaxf((float)deg, 1.f);
    const float logd = logf(dc + 1.f);
    const float a_s  = logd / AVG_DEG_LOG;
    const float t_s  = AVG_DEG_LOG / logd;

    int part = blockIdx.y;
    int tid = threadIdx.x;
    size_t sbase = (size_t)slot * D * KAGG;
    #pragma unroll
    for (int it = 0; it < 8; it++) {
        int idx = part * 8192 + it * 1024 + tid * 4;
        int j = idx >> 9;
        int k = idx & 511;
        const float* wb = Wm + (size_t)j * 1536 + k;
        float4 w0 = *(const float4*)(wb);
        float4 w1 = *(const float4*)(wb + 512);
        float4 w2 = *(const float4*)(wb + 1024);
        float f0 = w0.x + a_s * w1.x + t_s * w2.x;
        float f1 = w0.y + a_s * w1.y + t_s * w2.y;
        float f2 = w0.z + a_s * w1.z + t_s * w2.z;
        float f3 = w0.w + a_s * w1.w + t_s * w2.w;
        __half h0, h1, h2, h3, l0, l1, l2, l3;
        split16(f0, h0, l0); split16(f1, h1, l1);
        split16(f2, h2, l2); split16(f3, h3, l3);
        *(uint2*)&g_wf_hi[sbase + idx] = make_uint2(pkh16(h0, h1), pkh16(h2, h3));
        *(uint2*)&g_wf_lo[sbase + idx] = make_uint2(pkh16(l0, l1), pkh16(l2, l3));
    }
}

// ---------------- K7: gather aggregation (edge loop unrolled x2) ------------
__global__ void k_agg(const float* __restrict__ x) {
    int n = blockIdx.x * 8 + (threadIdx.x >> 5);
    if (n >= N_NODES) return;
    int lane = threadIdx.x & 31;
    int beg = g_off[n], end = g_off[n + 1];

    const float BIG = 3.402823466e38f;
    float4 sA  = make_float4(0.f, 0.f, 0.f, 0.f), sB  = make_float4(0.f, 0.f, 0.f, 0.f);
    float4 s2A = make_float4(0.f, 0.f, 0.f, 0.f), s2B = make_float4(0.f, 0.f, 0.f, 0.f);
    float4 mnA = make_float4( BIG,  BIG,  BIG,  BIG), mnB = mnA;
    float4 mxA = make_float4(-BIG, -BIG, -BIG, -BIG), mxB = mxA;

    int j = beg;
    for (; j + 1 < end; j += 2) {
        const float4* r0 = (const float4*)(x + (size_t)g_perm[j]     * D);
        const float4* r1 = (const float4*)(x + (size_t)g_perm[j + 1] * D);
        float4 v0 = r0[lane];
        float4 v1 = r1[lane];
        sA.x += v0.x; sA.y += v0.y; sA.z += v0.z; sA.w += v0.w;
        s2A.x += v0.x * v0.x; s2A.y += v0.y * v0.y; s2A.z += v0.z * v0.z; s2A.w += v0.w * v0.w;
        mnA.x = fminf(mnA.x, v0.x); mnA.y = fminf(mnA.y, v0.y); mnA.z = fminf(mnA.z, v0.z); mnA.w = fminf(mnA.w, v0.w);
        mxA.x = fmaxf(mxA.x, v0.x); mxA.y = fmaxf(mxA.y, v0.y); mxA.z = fmaxf(mxA.z, v0.z); mxA.w = fmaxf(mxA.w, v0.w);
        sB.x += v1.x; sB.y += v1.y; sB.z += v1.z; sB.w += v1.w;
        s2B.x += v1.x * v1.x; s2B.y += v1.y * v1.y; s2B.z += v1.z * v1.z; s2B.w += v1.w * v1.w;
        mnB.x = fminf(mnB.x, v1.x); mnB.y = fminf(mnB.y, v1.y); mnB.z = fminf(mnB.z, v1.z); mnB.w = fminf(mnB.w, v1.w);
        mxB.x = fmaxf(mxB.x, v1.x); mxB.y = fmaxf(mxB.y, v1.y); mxB.z = fmaxf(mxB.z, v1.z); mxB.w = fmaxf(mxB.w, v1.w);
    }
    if (j < end) {
        const float4* r0 = (const float4*)(x + (size_t)g_perm[j] * D);
        float4 v0 = r0[lane];
        sA.x += v0.x; sA.y += v0.y; sA.z += v0.z; sA.w += v0.w;
        s2A.x += v0.x * v0.x; s2A.y += v0.y * v0.y; s2A.z += v0.z * v0.z; s2A.w += v0.w * v0.w;
        mnA.x = fminf(mnA.x, v0.x); mnA.y = fminf(mnA.y, v0.y); mnA.z = fminf(mnA.z, v0.z); mnA.w = fminf(mnA.w, v0.w);
        mxA.x = fmaxf(mxA.x, v0.x); mxA.y = fmaxf(mxA.y, v0.y); mxA.z = fmaxf(mxA.z, v0.z); mxA.w = fmaxf(mxA.w, v0.w);
    }
    float4 s  = make_float4(sA.x + sB.x, sA.y + sB.y, sA.z + sB.z, sA.w + sB.w);
    float4 s2 = make_float4(s2A.x + s2B.x, s2A.y + s2B.y, s2A.z + s2B.z, s2A.w + s2B.w);
    float4 mn = make_float4(fminf(mnA.x, mnB.x), fminf(mnA.y, mnB.y), fminf(mnA.z, mnB.z), fminf(mnA.w, mnB.w));
    float4 mx = make_float4(fmaxf(mxA.x, mxB.x), fmaxf(mxA.y, mxB.y), fmaxf(mxA.z, mxB.z), fmaxf(mxA.w, mxB.w));

    int deg = end - beg;
    float c = fmaxf((float)deg, 1.f);
    float inv = 1.f / c;
    float4 mean = make_float4(s.x * inv, s.y * inv, s.z * inv, s.w * inv);
    float4 sd;
    sd.x = sqrtf(fmaxf(s2.x * inv - mean.x * mean.x, 0.f) + EPS_STD);
    sd.y = sqrtf(fmaxf(s2.y * inv - mean.y * mean.y, 0.f) + EPS_STD);
    sd.z = sqrtf(fmaxf(s2.z * inv - mean.z * mean.z, 0.f) + EPS_STD);
    sd.w = sqrtf(fmaxf(s2.w * inv - mean.w * mean.w, 0.f) + EPS_STD);
    if (deg == 0) {
        mn = make_float4(0.f, 0.f, 0.f, 0.f);
        mx = make_float4(0.f, 0.f, 0.f, 0.f);
    }
    size_t ob = (size_t)n * KAGG + lane * 4;
    float4 vals[4] = {mean, mn, mx, sd};
    #pragma unroll
    for (int sec = 0; sec < 4; sec++) {
        float4 v = vals[sec];
        __half h0, h1, h2, h3, l0, l1, l2, l3;
        split16(v.x, h0, l0); split16(v.y, h1, l1);
        split16(v.z, h2, l2); split16(v.w, h3, l3);
        *(uint2*)&g_agg_hi[ob + sec * 128] = make_uint2(pkh16(h0, h1), pkh16(h2, h3));
        *(uint2*)&g_agg_lo[ob + sec * 128] = make_uint2(pkh16(l0, l1), pkh16(l2, l3));
    }
}

// ---------------- K8: mma.sync GEMM, cp.async double-buffered ---------------
__global__ __launch_bounds__(256, 2) void k_gemm_mma(const float* __restrict__ bias,
                                                     float* __restrict__ out) {
    int t = blockIdx.x;
    if (t >= g_ntiles) return;

    extern __shared__ char dsm[];
    int* rid = (int*)(dsm + 2 * STAGE_BYTES);

    const int tid  = threadIdx.x;
    const int wid  = tid >> 5;
    const int lane = tid & 31;
    const int wr   = wid >> 1;
    const int wc   = wid & 1;
    const int g    = lane >> 2;
    const int tq   = lane & 3;

    const int start = g_tile_start[t];
    const int rows  = g_tile_rows[t];
    const int slot  = g_tile_slot[t] >= 0 ? g_tile_slot[t] : 0;

    if (tid < BM2) rid[tid] = (tid < rows) ? g_perm2[start + tid] : -1;
    __syncthreads();

    // per-thread copy mapping: 2 chunks of 16B per plane per k-tile
    // chunk c (c=tid, tid+256): row = c>>2, kq8 = (c&3)*8 halves
    const int r0 = tid >> 2,           kq0 = (tid & 3) * 8;
    const int r1 = (tid + 256) >> 2,   kq1 = kq0;   // (tid+256)&3 == tid&3
    const int nd0 = rid[r0], nd1 = rid[r1];
    const uint32_t sz0 = nd0 >= 0 ? 16u : 0u;
    const uint32_t sz1 = nd1 >= 0 ? 16u : 0u;
    const size_t a0 = (size_t)(nd0 >= 0 ? nd0 : 0) * KAGG + kq0;
    const size_t a1 = (size_t)(nd1 >= 0 ? nd1 : 0) * KAGG + kq1;
    const size_t w0 = (size_t)slot * D * KAGG + (size_t)r0 * KAGG + kq0;
    const size_t w1 = (size_t)slot * D * KAGG + (size_t)r1 * KAGG + kq1;
    const uint32_t d0 = (uint32_t)(r0 * (BKP * 2) + (tid & 3) * 16);
    const uint32_t d1 = (uint32_t)(r1 * (BKP * 2) + (tid & 3) * 16);
    const uint32_t smem0 = (uint32_t)__cvta_generic_to_shared(dsm);

    #define ISSUE_TILE(stg, kt) do {                                              \
        uint32_t sb_ = smem0 + (stg) * STAGE_BYTES;                               \
        CP16(sb_ + d0,                 g_agg_hi + a0 + (kt), sz0);                \
        CP16(sb_ + d1,                 g_agg_hi + a1 + (kt), sz1);                \
        CP16(sb_ + ARR_BYTES + d0,     g_agg_lo + a0 + (kt), sz0);                \
        CP16(sb_ + ARR_BYTES + d1,     g_agg_lo + a1 + (kt), sz1);                \
        CP16(sb_ + 2 * ARR_BYTES + d0, g_wf_hi + w0 + (kt), 16u);                 \
        CP16(sb_ + 2 * ARR_BYTES + d1, g_wf_hi + w1 + (kt), 16u);                 \
        CP16(sb_ + 3 * ARR_BYTES + d0, g_wf_lo + w0 + (kt), 16u);                 \
        CP16(sb_ + 3 * ARR_BYTES + d1, g_wf_lo + w1 + (kt), 16u);                 \
        CP_COMMIT();                                                              \
    } while (0)

    float acc[2][8][4];
    #pragma unroll
    for (int mt = 0; mt < 2; mt++)
        #pragma unroll
        for (int nt = 0; nt < 8; nt++)
            #pragma unroll
            for (int i = 0; i < 4; i++) acc[mt][nt][i] = 0.f;

    ISSUE_TILE(0, 0);

    int stg = 0;
    for (int kt = 0; kt < KAGG; kt += BKT) {
        const bool has_next = (kt + BKT < KAGG);
        if (has_next) {
            ISSUE_TILE(stg ^ 1, kt + BKT);
            CP_WAIT(1);
        } else {
            CP_WAIT(0);
        }
        __syncthreads();

        const uint16_t (*As_hi)[BKP] = (const uint16_t(*)[BKP])(dsm + stg * STAGE_BYTES);
        const uint16_t (*As_lo)[BKP] = (const uint16_t(*)[BKP])(dsm + stg * STAGE_BYTES + ARR_BYTES);
        const uint16_t (*Bs_hi)[BKP] = (const uint16_t(*)[BKP])(dsm + stg * STAGE_BYTES + 2 * ARR_BYTES);
        const uint16_t (*Bs_lo)[BKP] = (const uint16_t(*)[BKP])(dsm + stg * STAGE_BYTES + 3 * ARR_BYTES);

        #pragma unroll
        for (int ks = 0; ks < BKT; ks += 16) {
            int k0 = ks + 2 * tq;
            uint32_t bh[8][2], bl[8][2];
            #pragma unroll
            for (int nt = 0; nt < 8; nt++) {
                int colB = wc * 64 + nt * 8 + g;
                bh[nt][0] = *(const uint32_t*)&Bs_hi[colB][k0];
                bh[nt][1] = *(const uint32_t*)&Bs_hi[colB][k0 + 8];
                bl[nt][0] = *(const uint32_t*)&Bs_lo[colB][k0];
                bl[nt][1] = *(const uint32_t*)&Bs_lo[colB][k0 + 8];
            }
            #pragma unroll
            for (int mt = 0; mt < 2; mt++) {
                int rowA = wr * 32 + mt * 16 + g;
                uint32_t ah[4], al[4];
                ah[0] = *(const uint32_t*)&As_hi[rowA    ][k0];
                ah[1] = *(const uint32_t*)&As_hi[rowA + 8][k0];
                ah[2] = *(const uint32_t*)&As_hi[rowA    ][k0 + 8];
                ah[3] = *(const uint32_t*)&As_hi[rowA + 8][k0 + 8];
                al[0] = *(const uint32_t*)&As_lo[rowA    ][k0];
                al[1] = *(const uint32_t*)&As_lo[rowA + 8][k0];
                al[2] = *(const uint32_t*)&As_lo[rowA    ][k0 + 8];
                al[3] = *(const uint32_t*)&As_lo[rowA + 8][k0 + 8];
                #pragma unroll
                for (int nt = 0; nt < 8; nt++) {
                    mma16816(acc[mt][nt], ah, bh[nt]);
                    mma16816(acc[mt][nt], ah, bl[nt]);
                    mma16816(acc[mt][nt], al, bh[nt]);
                }
            }
        }
        __syncthreads();   // readers done before next issue overwrites this stage
        stg ^= 1;
    }

    // ---- epilogue ----
    #pragma unroll
    for (int mt = 0; mt < 2; mt++) {
        int row0 = wr * 32 + mt * 16 + g;
        int n0 = rid[row0];
        int n1 = rid[row0 + 8];
        #pragma unroll
        for (int nt = 0; nt < 8; nt++) {
            int col = wc * 64 + nt * 8 + 2 * tq;
            float b0 = bias[col], b1 = bias[col + 1];
            if (n0 >= 0) {
                float2 v0 = make_float2(acc[mt][nt][0] + b0, acc[mt][nt][1] + b1);
                *(float2*)(out + (size_t)n0 * D + col) = v0;
            }
            if (n1 >= 0) {
                float2 v1 = make_float2(acc[mt][nt][2] + b0, acc[mt][nt][3] + b1);
                *(float2*)(out + (size_t)n1 * D + col) = v1;
            }
        }
    }
}

// ---------------- launch ----------------------------------------------------
extern "C" void kernel_launch(void* const* d_in, const int* in_sizes, int n_in,
                              void* d_out, int out_size) {
    const float* x     = (const float*)d_in[0];
    const int*   index = (const int*)d_in[1];
    const float* W     = (const float*)d_in[2];
    const float* b     = (const float*)d_in[3];
    float* out = (float*)d_out;

    cudaFuncSetAttribute(k_gemm_mma, cudaFuncAttributeMaxDynamicSharedMemorySize, SMEM_GEMM);

    k_zero<<<(N_NODES + 255) / 256, 256>>>();
    k_count<<<(N_EDGES + 255) / 256, 256>>>(index);
    k_scan<<<1, 1024>>>();
    k_fill<<<(N_EDGES + 255) / 256, 256>>>(index);
    k_binscan<<<1, 1024>>>();
    k_prefold<<<dim3(MAX_SLOTS, 8), 256>>>(W);
    k_fill2<<<(N_NODES + 255) / 256, 256>>>();
    k_agg<<<(N_NODES + 7) / 8, 256>>>(x);
    k_gemm_mma<<<MAX_TILES, 256, SMEM_GEMM>>>(b, out);
}

// round 17
// speedup vs baseline: 2.0753x; 1.0715x over previous
#include <cuda_runtime.h>
#include <cuda_fp16.h>
#include <math.h>
#include <stdint.h>

#define N_NODES 50000
#define N_EDGES 800000
#define D 128
#define KAGG 512            // 4*D aggregate feature width
#define EPS_STD 1e-5f
#define AVG_DEG_LOG 2.8332133440562162f   // log(17)

#define NBINS 2048
#define BM2 128             // GEMM tile rows (nodes)
#define BKT 32              // K per smem tile
#define BKP 40              // padded half-stride (20 words: conflict-free frags)
#define MAX_TILES 2560
#define MAX_SLOTS 256
#define NSCAN ((N_NODES + 1023) / 1024)    // 49 scan blocks

#define ARR_BYTES (BM2 * BKP * 2)          // 10240 per plane
#define STAGE_BYTES (4 * ARR_BYTES)        // 40960
#define SMEM_GEMM (2 * STAGE_BYTES + 512)  // 82432

// ---------------- scratch (__device__ globals; no allocation allowed) -------
__device__ int      g_cnt[N_NODES];
__device__ int      g_off[N_NODES + 1];
__device__ int      g_woff[N_NODES];
__device__ int      g_perm[N_EDGES];
__device__ int      g_blk_sum[NSCAN];
__device__ int      g_blk_off[NSCAN];
__device__ uint16_t g_agg_hi[(size_t)N_NODES * KAGG];
__device__ uint16_t g_agg_lo[(size_t)N_NODES * KAGG];
__device__ int      g_bin_cnt[NBINS];
__device__ int      g_bin_off[NBINS + 1];
__device__ int      g_bin_w[NBINS];
__device__ int      g_perm2[N_NODES];
__device__ int      g_ntiles;
__device__ int      g_nslots;
__device__ int      g_slot_deg[MAX_SLOTS];
__device__ int      g_tile_start[MAX_TILES];
__device__ int      g_tile_rows[MAX_TILES];
__device__ int      g_tile_deg[MAX_TILES];
__device__ int      g_tile_slot[MAX_TILES];
__device__ uint16_t g_wf_hi[(size_t)MAX_SLOTS * D * KAGG];
__device__ uint16_t g_wf_lo[(size_t)MAX_SLOTS * D * KAGG];

// ---------------- helpers ----------------------------------------------------
__device__ __forceinline__ uint32_t pkh16(__half x, __half y) {
    return (uint32_t)(*(uint16_t*)&x) | ((uint32_t)(*(uint16_t*)&y) << 16);
}
__device__ __forceinline__ void mma16816(float* c, const uint32_t* a, const uint32_t* b) {
    asm volatile(
        "mma.sync.aligned.m16n8k16.row.col.f32.f16.f16.f32 "
        "{%0,%1,%2,%3}, {%4,%5,%6,%7}, {%8,%9}, {%0,%1,%2,%3};"
        : "+f"(c[0]), "+f"(c[1]), "+f"(c[2]), "+f"(c[3])
        : "r"(a[0]), "r"(a[1]), "r"(a[2]), "r"(a[3]), "r"(b[0]), "r"(b[1]));
}
__device__ __forceinline__ void split16(float v, __half& h, __half& l) {
    h = __float2half_rn(v);
    l = __float2half_rn(v - __half2float(h));
}
#define CP16(dst, src, sz) \
    asm volatile("cp.async.cg.shared.global [%0], [%1], 16, %2;" \
                 :: "r"(dst), "l"(src), "r"(sz) : "memory")
#define CP_COMMIT() asm volatile("cp.async.commit_group;" ::: "memory")
#define CP_WAIT(n)  asm volatile("cp.async.wait_group %0;" :: "n"(n) : "memory")

#define ACCUM(S, S2, MN, MX, V)                                                   \
    do {                                                                          \
        S.x += V.x; S.y += V.y; S.z += V.z; S.w += V.w;                           \
        S2.x += V.x * V.x; S2.y += V.y * V.y; S2.z += V.z * V.z; S2.w += V.w * V.w; \
        MN.x = fminf(MN.x, V.x); MN.y = fminf(MN.y, V.y);                         \
        MN.z = fminf(MN.z, V.z); MN.w = fminf(MN.w, V.w);                         \
        MX.x = fmaxf(MX.x, V.x); MX.y = fmaxf(MX.y, V.y);                         \
        MX.z = fmaxf(MX.z, V.z); MX.w = fmaxf(MX.w, V.w);                         \
    } while (0)

// ---------------- K0: zero counters -----------------------------------------
__global__ void k_zero() {
    int i = blockIdx.x * blockDim.x + threadIdx.x;
    if (i < N_NODES) g_cnt[i] = 0;
    if (i < NBINS)   g_bin_cnt[i] = 0;
    if (i == 0) { g_ntiles = 0; g_nslots = 0; }
}

// ---------------- K1: count degrees -----------------------------------------
__global__ void k_count(const int* __restrict__ index) {
    int e = blockIdx.x * blockDim.x + threadIdx.x;
    if (e < N_EDGES) atomicAdd(&g_cnt[index[e]], 1);
}

// ---------------- K2a: block-local scan + degree histogram ------------------
__global__ void k_scan1() {
    __shared__ int sh_warp[32];
    int b = blockIdx.x, tid = threadIdx.x, lane = tid & 31, wid = tid >> 5;
    int i = b * 1024 + tid;
    int v = (i < N_NODES) ? g_cnt[i] : 0;
    if (i < N_NODES) {
        int bb = v < NBINS ? v : NBINS - 1;
        atomicAdd(&g_bin_cnt[bb], 1);
    }
    int incl = v;
    #pragma unroll
    for (int d = 1; d < 32; d <<= 1) {
        int t = __shfl_up_sync(0xFFFFFFFFu, incl, d);
        if (lane >= d) incl += t;
    }
    if (lane == 31) sh_warp[wid] = incl;
    __syncthreads();
    if (wid == 0) {
        int w = sh_warp[lane];
        int wi = w;
        #pragma unroll
        for (int d = 1; d < 32; d <<= 1) {
            int t = __shfl_up_sync(0xFFFFFFFFu, wi, d);
            if (lane >= d) wi += t;
        }
        sh_warp[lane] = wi - w;
    }
    __syncthreads();
    int excl = incl - v + sh_warp[wid];
    if (i < N_NODES) g_off[i] = excl;
    if (tid == 1023) g_blk_sum[b] = excl + v;
}

// ---------------- K2b: scan block totals (49 values) ------------------------
__global__ void k_scan2() {
    __shared__ int wtot[2];
    int tid = threadIdx.x;            // 64 threads
    int lane = tid & 31, w = tid >> 5;
    int v = (tid < NSCAN) ? g_blk_sum[tid] : 0;
    int incl = v;
    #pragma unroll
    for (int d = 1; d < 32; d <<= 1) {
        int t = __shfl_up_sync(0xFFFFFFFFu, incl, d);
        if (lane >= d) incl += t;
    }
    if (lane == 31) wtot[w] = incl;
    __syncthreads();
    int add = (w == 1) ? wtot[0] : 0;
    int excl = incl - v + add;
    if (tid < NSCAN) g_blk_off[tid] = excl;
    if (tid == NSCAN - 1) g_off[N_NODES] = excl + v;
}

// ---------------- K2c: apply block offsets ----------------------------------
__global__ void k_scan3() {
    int i = blockIdx.x * blockDim.x + threadIdx.x;
    if (i < N_NODES) {
        int e = g_off[i] + g_blk_off[i >> 10];
        g_off[i] = e;
        g_woff[i] = e;
    }
}

// ---------------- K3: fill CSR permutation ----------------------------------
__global__ void k_fill(const int* __restrict__ index) {
    int e = blockIdx.x * blockDim.x + threadIdx.x;
    if (e < N_EDGES) {
        int node = index[e];
        int pos = atomicAdd(&g_woff[node], 1);
        g_perm[pos] = e;
    }
}

// ---------------- K4: bin scan + slot assignment + tile table ---------------
__global__ void k_binscan() {
    __shared__ int sh_warp[32];
    __shared__ int sh_carry;
    int tid = threadIdx.x, lane = tid & 31, wid = tid >> 5;
    if (tid == 0) sh_carry = 0;
    __syncthreads();
    for (int base = 0; base < NBINS; base += 1024) {
        int i = base + tid;
        int v = (i < NBINS) ? g_bin_cnt[i] : 0;
        int incl = v;
        #pragma unroll
        for (int d = 1; d < 32; d <<= 1) {
            int t = __shfl_up_sync(0xFFFFFFFFu, incl, d);
            if (lane >= d) incl += t;
        }
        if (lane == 31) sh_warp[wid] = incl;
        __syncthreads();
        if (wid == 0) {
            int w = sh_warp[lane];
            int wi = w;
            #pragma unroll
            for (int d = 1; d < 32; d <<= 1) {
                int t = __shfl_up_sync(0xFFFFFFFFu, wi, d);
                if (lane >= d) wi += t;
            }
            sh_warp[lane] = wi - w;
        }
        __syncthreads();
        int excl = incl - v + sh_warp[wid] + sh_carry;
        if (i < NBINS) { g_bin_off[i] = excl; g_bin_w[i] = 0; }
        __syncthreads();
        if (tid == 1023) sh_carry = excl + v;
        __syncthreads();
    }
    if (tid == 0) g_bin_off[NBINS] = sh_carry;
    __syncthreads();
    for (int b = tid; b < NBINS; b += 1024) {
        int base = g_bin_off[b];
        int cnt = g_bin_off[b + 1] - base;
        if (cnt > 0) {
            int slot = atomicAdd(&g_nslots, 1);
            if (slot < MAX_SLOTS) g_slot_deg[slot] = b;
            else slot = -1;
            for (int j = 0; j < cnt; j += BM2) {
                int idx = atomicAdd(&g_ntiles, 1);
                g_tile_start[idx] = base + j;
                g_tile_rows[idx]  = (cnt - j < BM2) ? (cnt - j) : BM2;
                g_tile_deg[idx]   = b;
                g_tile_slot[idx]  = slot;
            }
        }
    }
}

// ---------------- K5: scatter nodes into degree buckets ---------------------
__global__ void k_fill2() {
    int n = blockIdx.x * blockDim.x + threadIdx.x;
    if (n < N_NODES) {
        int deg = g_cnt[n];
        int b = deg < NBINS ? deg : NBINS - 1;
        int pos = atomicAdd(&g_bin_w[b], 1);
        g_perm2[g_bin_off[b] + pos] = n;
    }
}

// ---------------- K6: pre-fold W per slot into fp16 hi/lo -------------------
__global__ void k_prefold(const float* __restrict__ Wm) {
    int slot = blockIdx.x;
    if (slot >= g_nslots || slot >= MAX_SLOTS) return;
    int deg = g_slot_deg[slot];
    const float dc   = fmaxf((float)deg, 1.f);
    const float logd = logf(dc + 1.f);
    const float a_s  = logd / AVG_DEG_LOG;
    const float t_s  = AVG_DEG_LOG / logd;

    int part = blockIdx.y;
    int tid = threadIdx.x;
    size_t sbase = (size_t)slot * D * KAGG;
    #pragma unroll
    for (int it = 0; it < 8; it++) {
        int idx = part * 8192 + it * 1024 + tid * 4;
        int j = idx >> 9;
        int k = idx & 511;
        const float* wb = Wm + (size_t)j * 1536 + k;
        float4 w0 = *(const float4*)(wb);
        float4 w1 = *(const float4*)(wb + 512);
        float4 w2 = *(const float4*)(wb + 1024);
        float f0 = w0.x + a_s * w1.x + t_s * w2.x;
        float f1 = w0.y + a_s * w1.y + t_s * w2.y;
        float f2 = w0.z + a_s * w1.z + t_s * w2.z;
        float f3 = w0.w + a_s * w1.w + t_s * w2.w;
        __half h0, h1, h2, h3, l0, l1, l2, l3;
        split16(f0, h0, l0); split16(f1, h1, l1);
        split16(f2, h2, l2); split16(f3, h3, l3);
        *(uint2*)&g_wf_hi[sbase + idx] = make_uint2(pkh16(h0, h1), pkh16(h2, h3));
        *(uint2*)&g_wf_lo[sbase + idx] = make_uint2(pkh16(l0, l1), pkh16(l2, l3));
    }
}

// ---------------- K7: gather aggregation (4 rows in flight) -----------------
__global__ void k_agg(const float* __restrict__ x) {
    int n = blockIdx.x * 8 + (threadIdx.x >> 5);
    if (n >= N_NODES) return;
    int lane = threadIdx.x & 31;
    int beg = g_off[n], end = g_off[n + 1];

    const float BIG = 3.402823466e38f;
    float4 sA  = make_float4(0.f, 0.f, 0.f, 0.f), sB  = sA;
    float4 s2A = sA, s2B = sA;
    float4 mnA = make_float4( BIG,  BIG,  BIG,  BIG), mnB = mnA;
    float4 mxA = make_float4(-BIG, -BIG, -BIG, -BIG), mxB = mxA;

    int j = beg;
    for (; j + 3 < end; j += 4) {
        int p0 = g_perm[j], p1 = g_perm[j + 1], p2 = g_perm[j + 2], p3 = g_perm[j + 3];
        float4 v0 = ((const float4*)(x + (size_t)p0 * D))[lane];
        float4 v1 = ((const float4*)(x + (size_t)p1 * D))[lane];
        float4 v2 = ((const float4*)(x + (size_t)p2 * D))[lane];
        float4 v3 = ((const float4*)(x + (size_t)p3 * D))[lane];
        ACCUM(sA, s2A, mnA, mxA, v0);
        ACCUM(sB, s2B, mnB, mxB, v1);
        ACCUM(sA, s2A, mnA, mxA, v2);
        ACCUM(sB, s2B, mnB, mxB, v3);
    }
    for (; j < end; j++) {
        float4 v0 = ((const float4*)(x + (size_t)g_perm[j] * D))[lane];
        ACCUM(sA, s2A, mnA, mxA, v0);
    }
    float4 s  = make_float4(sA.x + sB.x, sA.y + sB.y, sA.z + sB.z, sA.w + sB.w);
    float4 s2 = make_float4(s2A.x + s2B.x, s2A.y + s2B.y, s2A.z + s2B.z, s2A.w + s2B.w);
    float4 mn = make_float4(fminf(mnA.x, mnB.x), fminf(mnA.y, mnB.y), fminf(mnA.z, mnB.z), fminf(mnA.w, mnB.w));
    float4 mx = make_float4(fmaxf(mxA.x, mxB.x), fmaxf(mxA.y, mxB.y), fmaxf(mxA.z, mxB.z), fmaxf(mxA.w, mxB.w));

    int deg = end - beg;
    float c = fmaxf((float)deg, 1.f);
    float inv = 1.f / c;
    float4 mean = make_float4(s.x * inv, s.y * inv, s.z * inv, s.w * inv);
    float4 sd;
    sd.x = sqrtf(fmaxf(s2.x * inv - mean.x * mean.x, 0.f) + EPS_STD);
    sd.y = sqrtf(fmaxf(s2.y * inv - mean.y * mean.y, 0.f) + EPS_STD);
    sd.z = sqrtf(fmaxf(s2.z * inv - mean.z * mean.z, 0.f) + EPS_STD);
    sd.w = sqrtf(fmaxf(s2.w * inv - mean.w * mean.w, 0.f) + EPS_STD);
    if (deg == 0) {
        mn = make_float4(0.f, 0.f, 0.f, 0.f);
        mx = make_float4(0.f, 0.f, 0.f, 0.f);
    }
    size_t ob = (size_t)n * KAGG + lane * 4;
    float4 vals[4] = {mean, mn, mx, sd};
    #pragma unroll
    for (int sec = 0; sec < 4; sec++) {
        float4 v = vals[sec];
        __half h0, h1, h2, h3, l0, l1, l2, l3;
        split16(v.x, h0, l0); split16(v.y, h1, l1);
        split16(v.z, h2, l2); split16(v.w, h3, l3);
        *(uint2*)&g_agg_hi[ob + sec * 128] = make_uint2(pkh16(h0, h1), pkh16(h2, h3));
        *(uint2*)&g_agg_lo[ob + sec * 128] = make_uint2(pkh16(l0, l1), pkh16(l2, l3));
    }
}

// ---------------- K8: mma.sync GEMM, cp.async double-buffered ---------------
__global__ __launch_bounds__(256, 2) void k_gemm_mma(const float* __restrict__ bias,
                                                     float* __restrict__ out) {
    int t = blockIdx.x;
    if (t >= g_ntiles) return;

    extern __shared__ char dsm[];
    int* rid = (int*)(dsm + 2 * STAGE_BYTES);

    const int tid  = threadIdx.x;
    const int wid  = tid >> 5;
    const int lane = tid & 31;
    const int wr   = wid >> 1;
    const int wc   = wid & 1;
    const int g    = lane >> 2;
    const int tq   = lane & 3;

    const int start = g_tile_start[t];
    const int rows  = g_tile_rows[t];
    const int slot  = g_tile_slot[t] >= 0 ? g_tile_slot[t] : 0;

    if (tid < BM2) rid[tid] = (tid < rows) ? g_perm2[start + tid] : -1;
    __syncthreads();

    const int r0 = tid >> 2,           kq0 = (tid & 3) * 8;
    const int r1 = (tid + 256) >> 2,   kq1 = kq0;
    const int nd0 = rid[r0], nd1 = rid[r1];
    const uint32_t sz0 = nd0 >= 0 ? 16u : 0u;
    const uint32_t sz1 = nd1 >= 0 ? 16u : 0u;
    const size_t a0 = (size_t)(nd0 >= 0 ? nd0 : 0) * KAGG + kq0;
    const size_t a1 = (size_t)(nd1 >= 0 ? nd1 : 0) * KAGG + kq1;
    const size_t w0 = (size_t)slot * D * KAGG + (size_t)r0 * KAGG + kq0;
    const size_t w1 = (size_t)slot * D * KAGG + (size_t)r1 * KAGG + kq1;
    const uint32_t d0 = (uint32_t)(r0 * (BKP * 2) + (tid & 3) * 16);
    const uint32_t d1 = (uint32_t)(r1 * (BKP * 2) + (tid & 3) * 16);
    const uint32_t smem0 = (uint32_t)__cvta_generic_to_shared(dsm);

    #define ISSUE_TILE(stg, kt) do {                                              \
        uint32_t sb_ = smem0 + (stg) * STAGE_BYTES;                               \
        CP16(sb_ + d0,                 g_agg_hi + a0 + (kt), sz0);                \
        CP16(sb_ + d1,                 g_agg_hi + a1 + (kt), sz1);                \
        CP16(sb_ + ARR_BYTES + d0,     g_agg_lo + a0 + (kt), sz0);                \
        CP16(sb_ + ARR_BYTES + d1,     g_agg_lo + a1 + (kt), sz1);                \
        CP16(sb_ + 2 * ARR_BYTES + d0, g_wf_hi + w0 + (kt), 16u);                 \
        CP16(sb_ + 2 * ARR_BYTES + d1, g_wf_hi + w1 + (kt), 16u);                 \
        CP16(sb_ + 3 * ARR_BYTES + d0, g_wf_lo + w0 + (kt), 16u);                 \
        CP16(sb_ + 3 * ARR_BYTES + d1, g_wf_lo + w1 + (kt), 16u);                 \
        CP_COMMIT();                                                              \
    } while (0)

    float acc[2][8][4];
    #pragma unroll
    for (int mt = 0; mt < 2; mt++)
        #pragma unroll
        for (int nt = 0; nt < 8; nt++)
            #pragma unroll
            for (int i = 0; i < 4; i++) acc[mt][nt][i] = 0.f;

    ISSUE_TILE(0, 0);

    int stg = 0;
    for (int kt = 0; kt < KAGG; kt += BKT) {
        const bool has_next = (kt + BKT < KAGG);
        if (has_next) {
            ISSUE_TILE(stg ^ 1, kt + BKT);
            CP_WAIT(1);
        } else {
            CP_WAIT(0);
        }
        __syncthreads();

        const uint16_t (*As_hi)[BKP] = (const uint16_t(*)[BKP])(dsm + stg * STAGE_BYTES);
        const uint16_t (*As_lo)[BKP] = (const uint16_t(*)[BKP])(dsm + stg * STAGE_BYTES + ARR_BYTES);
        const uint16_t (*Bs_hi)[BKP] = (const uint16_t(*)[BKP])(dsm + stg * STAGE_BYTES + 2 * ARR_BYTES);
        const uint16_t (*Bs_lo)[BKP] = (const uint16_t(*)[BKP])(dsm + stg * STAGE_BYTES + 3 * ARR_BYTES);

        #pragma unroll
        for (int ks = 0; ks < BKT; ks += 16) {
            int k0 = ks + 2 * tq;
            uint32_t bh[8][2], bl[8][2];
            #pragma unroll
            for (int nt = 0; nt < 8; nt++) {
                int colB = wc * 64 + nt * 8 + g;
                bh[nt][0] = *(const uint32_t*)&Bs_hi[colB][k0];
                bh[nt][1] = *(const uint32_t*)&Bs_hi[colB][k0 + 8];
                bl[nt][0] = *(const uint32_t*)&Bs_lo[colB][k0];
                bl[nt][1] = *(const uint32_t*)&Bs_lo[colB][k0 + 8];
            }
            #pragma unroll
            for (int mt = 0; mt < 2; mt++) {
                int rowA = wr * 32 + mt * 16 + g;
                uint32_t ah[4], al[4];
                ah[0] = *(const uint32_t*)&As_hi[rowA    ][k0];
                ah[1] = *(const uint32_t*)&As_hi[rowA + 8][k0];
                ah[2] = *(const uint32_t*)&As_hi[rowA    ][k0 + 8];
                ah[3] = *(const uint32_t*)&As_hi[rowA + 8][k0 + 8];
                al[0] = *(const uint32_t*)&As_lo[rowA    ][k0];
                al[1] = *(const uint32_t*)&As_lo[rowA + 8][k0];
                al[2] = *(const uint32_t*)&As_lo[rowA    ][k0 + 8];
                al[3] = *(const uint32_t*)&As_lo[rowA + 8][k0 + 8];
                #pragma unroll
                for (int nt = 0; nt < 8; nt++) {
                    mma16816(acc[mt][nt], ah, bh[nt]);
                    mma16816(acc[mt][nt], ah, bl[nt]);
                    mma16816(acc[mt][nt], al, bh[nt]);
                }
            }
        }
        __syncthreads();
        stg ^= 1;
    }

    // ---- epilogue ----
    #pragma unroll
    for (int mt = 0; mt < 2; mt++) {
        int row0 = wr * 32 + mt * 16 + g;
        int n0 = rid[row0];
        int n1 = rid[row0 + 8];
        #pragma unroll
        for (int nt = 0; nt < 8; nt++) {
            int col = wc * 64 + nt * 8 + 2 * tq;
            float b0 = bias[col], b1 = bias[col + 1];
            if (n0 >= 0) {
                float2 v0 = make_float2(acc[mt][nt][0] + b0, acc[mt][nt][1] + b1);
                *(float2*)(out + (size_t)n0 * D + col) = v0;
            }
            if (n1 >= 0) {
                float2 v1 = make_float2(acc[mt][nt][2] + b0, acc[mt][nt][3] + b1);
                *(float2*)(out + (size_t)n1 * D + col) = v1;
            }
        }
    }
}

// ---------------- launch ----------------------------------------------------
extern "C" void kernel_launch(void* const* d_in, const int* in_sizes, int n_in,
                              void* d_out, int out_size) {
    const float* x     = (const float*)d_in[0];
    const int*   index = (const int*)d_in[1];
    const float* W     = (const float*)d_in[2];
    const float* b     = (const float*)d_in[3];
    float* out = (float*)d_out;

    cudaFuncSetAttribute(k_gemm_mma, cudaFuncAttributeMaxDynamicSharedMemorySize, SMEM_GEMM);

    k_zero<<<(N_NODES + 255) / 256, 256>>>();
    k_count<<<(N_EDGES + 255) / 256, 256>>>(index);
    k_scan1<<<NSCAN, 1024>>>();
    k_scan2<<<1, 64>>>();
    k_scan3<<<(N_NODES + 255) / 256, 256>>>();
    k_fill<<<(N_EDGES + 255) / 256, 256>>>(index);
    k_binscan<<<1, 1024>>>();
    k_prefold<<<dim3(MAX_SLOTS, 8), 256>>>(W);
    k_fill2<<<(N_NODES + 255) / 256, 256>>>();
    k_agg<<<(N_NODES + 7) / 8, 256>>>(x);
    k_gemm_mma<<<MAX_TILES, 256, SMEM_GEMM>>>(b, out);
}